// round 2
// baseline (speedup 1.0000x reference)
#include <cuda_runtime.h>
#include <math.h>

// Problem constants
#define B_    64
#define S_    2048
#define H_    1024
#define NH_   16
#define HD_   64
#define V_    50257
#define MAXLEN_ 1024
#define SLD_  2048            // scores leading dim (max context)
#define SCALE_ 0.125f         // HD^-0.5

// ---------------- scratch (module-load allocated, not runtime alloc) ----------
#define OF_EMB   ((size_t)0)
#define OF_Q     (OF_EMB  + (size_t)B_*H_)
#define OF_QT    (OF_Q    + (size_t)B_*H_)
#define OF_QC    (OF_QT   + (size_t)B_*NH_*H_)
#define OF_SC    (OF_QC   + (size_t)1024)
#define OF_CTX   (OF_SC   + (size_t)B_*NH_*SLD_)
#define OF_SAO   (OF_CTX  + (size_t)B_*NH_*H_)
#define OF_CAO   (OF_SAO  + (size_t)B_*H_)
#define OF_GATE  (OF_CAO  + (size_t)B_*H_)
#define SCRATCH_ (OF_GATE + (size_t)B_*4*H_)

__device__ float g_scratch[SCRATCH_];

// ---------------- embedding gather ----------------
__global__ void k_gather(const int* __restrict__ tok,
                         const float* __restrict__ table,
                         float* __restrict__ out)
{
    int b = blockIdx.x;
    int t = tok[b];
    const float4* src = (const float4*)(table + (size_t)t * H_);
    float4* dst = (float4*)(out + (size_t)b * H_);
    for (int i = threadIdx.x; i < H_/4; i += blockDim.x) dst[i] = src[i];
}

// ---------------- generic tiled SGEMM: C[64 x N] = A[64 x K] @ B[N x K]^T (+bias) ----
// M fixed at 64. Optional batch dim via grid.y with independent strides.
__global__ void k_gemm(const float* __restrict__ A, int lda, long long sA,
                       const float* __restrict__ Bw, int ldb, long long sB,
                       const float* __restrict__ bias, long long sBias,
                       float* __restrict__ C, int ldc, long long sC,
                       int N, int K, int accum)
{
    int bat = blockIdx.y;
    A  += (size_t)bat * sA;
    Bw += (size_t)bat * sB;
    C  += (size_t)bat * sC;
    if (bias) bias += (size_t)bat * sBias;

    int n0 = blockIdx.x * 64;
    __shared__ float As[32][65];
    __shared__ float Bs[32][65];

    int tid = threadIdx.x;
    int tm = (tid / 16) * 4;
    int tn = (tid % 16) * 4;
    int kk = tid % 32;
    int r  = tid / 32;       // 0..7

    float acc[4][4] = {};

    for (int k0 = 0; k0 < K; k0 += 32) {
#pragma unroll
        for (int p = 0; p < 8; p++) {
            int m = r + p * 8;
            As[kk][m] = A[(size_t)m * lda + k0 + kk];
        }
#pragma unroll
        for (int p = 0; p < 8; p++) {
            int nl = r + p * 8;
            int n = n0 + nl;
            Bs[kk][nl] = (n < N) ? Bw[(size_t)n * ldb + k0 + kk] : 0.f;
        }
        __syncthreads();
#pragma unroll
        for (int q = 0; q < 32; q++) {
            float a0 = As[q][tm+0], a1 = As[q][tm+1], a2 = As[q][tm+2], a3 = As[q][tm+3];
            float b0 = Bs[q][tn+0], b1 = Bs[q][tn+1], b2 = Bs[q][tn+2], b3 = Bs[q][tn+3];
            acc[0][0] += a0*b0; acc[0][1] += a0*b1; acc[0][2] += a0*b2; acc[0][3] += a0*b3;
            acc[1][0] += a1*b0; acc[1][1] += a1*b1; acc[1][2] += a1*b2; acc[1][3] += a1*b3;
            acc[2][0] += a2*b0; acc[2][1] += a2*b1; acc[2][2] += a2*b2; acc[2][3] += a2*b3;
            acc[3][0] += a3*b0; acc[3][1] += a3*b1; acc[3][2] += a3*b2; acc[3][3] += a3*b3;
        }
        __syncthreads();
    }

#pragma unroll
    for (int i = 0; i < 4; i++) {
#pragma unroll
        for (int j = 0; j < 4; j++) {
            int n = n0 + tn + j;
            if (n < N) {
                float v = acc[i][j] + (bias ? bias[n] : 0.f);
                size_t idx = (size_t)(tm + i) * ldc + n;
                if (accum) C[idx] += v; else C[idx] = v;
            }
        }
    }
}

// ---------------- q-tilde fold: qt[b,h,d] = sum_j Q[b,h*64+j] * Wk[h*64+j,d]
//                  qc[b,h]   = sum_j Q[b,h*64+j] * bk[h*64+j]
__global__ void k_qt(const float* __restrict__ Q,
                     const float* __restrict__ Wk,
                     const float* __restrict__ bk,
                     float* __restrict__ qt,
                     float* __restrict__ qc)
{
    int h = blockIdx.y;
    int d = blockIdx.x * 64 + (threadIdx.x % 64);
    int bg = threadIdx.x / 64;      // 0..3, each owns 16 batches

    __shared__ float Qs[64][65];
    for (int i = threadIdx.x; i < 64*64; i += 256) {
        int b = i / 64, j = i % 64;
        Qs[b][j] = Q[(size_t)b * H_ + h * 64 + j];
    }
    __syncthreads();

    float acc[16] = {};
#pragma unroll 4
    for (int j = 0; j < 64; j++) {
        float w = Wk[(size_t)(h * 64 + j) * H_ + d];
#pragma unroll
        for (int bb = 0; bb < 16; bb++) acc[bb] += Qs[bg*16 + bb][j] * w;
    }
#pragma unroll
    for (int bb = 0; bb < 16; bb++) {
        int b = bg * 16 + bb;
        qt[((size_t)b * NH_ + h) * H_ + d] = acc[bb];
    }
    if (blockIdx.x == 0 && threadIdx.x < 64) {
        int b = threadIdx.x;
        float s = 0.f;
        for (int j = 0; j < 64; j++) s += Qs[b][j] * bk[h * 64 + j];
        qc[b * NH_ + h] = s;
    }
}

// ---------------- scores[b,h,k] = (qt[b,h,:] . keys[b,k,:] + qc[b,h]) * SCALE, k < L
__global__ void k_scores(const float* __restrict__ qt,
                         const float* __restrict__ qc,
                         const float* __restrict__ keys, long long kbstride,
                         float* __restrict__ scores,
                         int Lmax, const int* __restrict__ Lptr)
{
    int b = blockIdx.y;
    int L = Lptr ? Lptr[0] : Lmax;
    int k0 = blockIdx.x * 32;
    if (k0 >= L) return;

    __shared__ float qs[16][65];
    __shared__ float ks[32][65];

    int tid = threadIdx.x;
    int kl = tid % 32;
    int hg = tid / 32;          // 0..7; owns heads hg and hg+8
    float acc0 = 0.f, acc1 = 0.f;
    const float* kb = keys + (size_t)b * kbstride;

    for (int d0 = 0; d0 < H_; d0 += 64) {
        for (int i = tid; i < 16*64; i += 256) {
            int h = i / 64, dd = i % 64;
            qs[h][dd] = qt[((size_t)b * NH_ + h) * H_ + d0 + dd];
        }
        for (int i = tid; i < 32*16; i += 256) {
            int rr = i / 16, dq = i % 16;
            float4 v = *(const float4*)&kb[(size_t)(k0 + rr) * H_ + d0 + dq * 4];
            ks[rr][dq*4+0] = v.x; ks[rr][dq*4+1] = v.y;
            ks[rr][dq*4+2] = v.z; ks[rr][dq*4+3] = v.w;
        }
        __syncthreads();
#pragma unroll
        for (int dd = 0; dd < 64; dd++) {
            float kv = ks[kl][dd];
            acc0 += qs[hg    ][dd] * kv;
            acc1 += qs[hg + 8][dd] * kv;
        }
        __syncthreads();
    }

    int k = k0 + kl;
    if (k < L) {
        scores[((size_t)b * NH_ + hg    ) * SLD_ + k] = (acc0 + qc[b*NH_ + hg    ]) * SCALE_;
        scores[((size_t)b * NH_ + hg + 8) * SLD_ + k] = (acc1 + qc[b*NH_ + hg + 8]) * SCALE_;
    }
}

// ---------------- softmax over k < L, row = (b*NH+h)
__global__ void k_softmax(float* __restrict__ scores,
                          int Lmax, const int* __restrict__ Lptr)
{
    int L = Lptr ? Lptr[0] : Lmax;
    float* s = scores + (size_t)blockIdx.x * SLD_;
    int tid = threadIdx.x;

    float v[8];
    float mx = -1e30f;
#pragma unroll
    for (int i = 0; i < 8; i++) {
        int k = tid + i * 256;
        v[i] = (k < L) ? s[k] : -1e30f;
        mx = fmaxf(mx, v[i]);
    }
    __shared__ float red[256];
    red[tid] = mx; __syncthreads();
    for (int off = 128; off; off >>= 1) {
        if (tid < off) red[tid] = fmaxf(red[tid], red[tid + off]);
        __syncthreads();
    }
    mx = red[0]; __syncthreads();

    float sum = 0.f;
#pragma unroll
    for (int i = 0; i < 8; i++) { v[i] = __expf(v[i] - mx); sum += v[i]; }
    red[tid] = sum; __syncthreads();
    for (int off = 128; off; off >>= 1) {
        if (tid < off) red[tid] += red[tid + off];
        __syncthreads();
    }
    float inv = 1.f / red[0];
#pragma unroll
    for (int i = 0; i < 8; i++) {
        int k = tid + i * 256;
        if (k < L) s[k] = v[i] * inv;
    }
}

// ---------------- ctx[b,h,d] = sum_{k<L} w[b,h,k] * keys[b,k,d]
__global__ void k_ctx(const float* __restrict__ w,
                      const float* __restrict__ keys, long long kbstride,
                      float* __restrict__ ctx,
                      int Lmax, const int* __restrict__ Lptr)
{
    int b = blockIdx.y;
    int d0 = blockIdx.x * 128;
    int L = Lptr ? Lptr[0] : Lmax;
    int tid = threadIdx.x;
    int dl = tid % 128;
    int hg = tid / 128;          // 0/1 -> heads hg*8 .. hg*8+7

    __shared__ float ws[16][33];
    __shared__ float ks[32][128];

    const float* kb = keys + (size_t)b * kbstride;
    float acc[8] = {};

    for (int k0 = 0; k0 < L; k0 += 32) {
        for (int i = tid; i < 16*32; i += 256) {
            int h = i / 32, kk = i % 32;
            int k = k0 + kk;
            ws[h][kk] = (k < L) ? w[((size_t)b * NH_ + h) * SLD_ + k] : 0.f;
        }
        for (int i = tid; i < 32*32; i += 256) {
            int rr = i / 32, dq = i % 32;
            float4 v = *(const float4*)&kb[(size_t)(k0 + rr) * H_ + d0 + dq * 4];
            ((float4*)&ks[rr][0])[dq] = v;
        }
        __syncthreads();
#pragma unroll
        for (int kk = 0; kk < 32; kk++) {
            float kv = ks[kk][dl];
#pragma unroll
            for (int hh = 0; hh < 8; hh++) acc[hh] += ws[hg*8 + hh][kk] * kv;
        }
        __syncthreads();
    }
#pragma unroll
    for (int hh = 0; hh < 8; hh++) {
        int h = hg * 8 + hh;
        ctx[((size_t)b * NH_ + h) * H_ + d0 + dl] = acc[hh];
    }
}

// ---------------- LSTM elementwise ----------------
__device__ __forceinline__ float sigm(float x) { return 1.f / (1.f + __expf(-x)); }

__global__ void k_lstm(const float* __restrict__ gates,
                       const float* __restrict__ bih,
                       const float* __restrict__ bhh,
                       const float* __restrict__ c_in,
                       float* __restrict__ out)
{
    int idx = blockIdx.x * 256 + threadIdx.x;
    if (idx >= B_ * H_) return;
    int b = idx / H_, o = idx % H_;
    const float* g = gates + (size_t)b * 4 * H_;

    float ig = sigm (g[0*H_ + o] + bih[0*H_ + o] + bhh[0*H_ + o]);
    float fg = sigm (g[1*H_ + o] + bih[1*H_ + o] + bhh[1*H_ + o]);
    float gg = tanhf(g[2*H_ + o] + bih[2*H_ + o] + bhh[2*H_ + o]);
    float og = sigm (g[3*H_ + o] + bih[3*H_ + o] + bhh[3*H_ + o]);

    float c = fg * c_in[idx] + ig * gg;
    float h = og * tanhf(c);

    out[(size_t)B_ * V_ + idx] = h;                       // h_new
    out[(size_t)B_ * V_ + (size_t)B_ * H_ + idx] = c;     // c_new
}

// ---------------- launcher ----------------
extern "C" void kernel_launch(void* const* d_in, const int* in_sizes, int n_in,
                              void* d_out, int out_size)
{
    const int*   tok   = (const int*)  d_in[0];
    const float* enc   = (const float*)d_in[1];
    const float* h_in  = (const float*)d_in[2];
    const float* c_in  = (const float*)d_in[3];
    const float* cache = (const float*)d_in[4];
    const int*   stepp = (const int*)  d_in[5];
    const float* table = (const float*)d_in[6];
    const float* saqw = (const float*)d_in[7];
    const float* saqb = (const float*)d_in[8];
    const float* sakw = (const float*)d_in[9];
    const float* sakb = (const float*)d_in[10];
    const float* savw = (const float*)d_in[11];
    const float* savb = (const float*)d_in[12];
    const float* caqw = (const float*)d_in[13];
    const float* caqb = (const float*)d_in[14];
    const float* cakw = (const float*)d_in[15];
    const float* cakb = (const float*)d_in[16];
    const float* cavw = (const float*)d_in[17];
    const float* cavb = (const float*)d_in[18];
    const float* wih  = (const float*)d_in[19];
    const float* bih  = (const float*)d_in[20];
    const float* whh  = (const float*)d_in[21];
    const float* bhh  = (const float*)d_in[22];
    const float* fcw  = (const float*)d_in[23];
    const float* fcb  = (const float*)d_in[24];
    float* out = (float*)d_out;

    float* sb = nullptr;
    cudaGetSymbolAddress((void**)&sb, g_scratch);

    float* p_emb  = sb + OF_EMB;
    float* p_Q    = sb + OF_Q;
    float* p_qt   = sb + OF_QT;
    float* p_qc   = sb + OF_QC;
    float* p_sc   = sb + OF_SC;
    float* p_ctx  = sb + OF_CTX;
    float* p_sao  = sb + OF_SAO;
    float* p_cao  = sb + OF_CAO;
    float* p_gate = sb + OF_GATE;
    float* p_hnew = out + (size_t)B_ * V_;

    // 1. embedding gather
    k_gather<<<B_, 256>>>(tok, table, p_emb);

    // ---- self-attention (keys/values = kv_cache[:, :step]) ----
    // Q_sa = emb @ sa_q_w^T + b
    k_gemm<<<dim3(H_/64, 1), 256>>>(p_emb, H_, 0, saqw, H_, 0, saqb, 0,
                                    p_Q, H_, 0, H_, H_, 0);
    k_qt<<<dim3(H_/64, NH_), 256>>>(p_Q, sakw, sakb, p_qt, p_qc);
    k_scores<<<dim3(MAXLEN_/32, B_), 256>>>(p_qt, p_qc, cache,
                                            (long long)MAXLEN_ * H_,
                                            p_sc, MAXLEN_, stepp);
    k_softmax<<<B_ * NH_, 256>>>(p_sc, MAXLEN_, stepp);
    k_ctx<<<dim3(H_/128, B_), 256>>>(p_sc, cache, (long long)MAXLEN_ * H_,
                                     p_ctx, MAXLEN_, stepp);
    // per-head V projection: batched over heads via grid.y
    k_gemm<<<dim3(1, NH_), 256>>>(p_ctx, NH_*H_, (long long)H_,
                                  savw, H_, (long long)HD_*H_,
                                  savb, HD_,
                                  p_sao, H_, (long long)HD_,
                                  HD_, H_, 0);

    // ---- cross-attention (keys/values = encoder_outputs) ----
    k_gemm<<<dim3(H_/64, 1), 256>>>(p_sao, H_, 0, caqw, H_, 0, caqb, 0,
                                    p_Q, H_, 0, H_, H_, 0);
    k_qt<<<dim3(H_/64, NH_), 256>>>(p_Q, cakw, cakb, p_qt, p_qc);
    k_scores<<<dim3(S_/32, B_), 256>>>(p_qt, p_qc, enc,
                                       (long long)S_ * H_,
                                       p_sc, S_, nullptr);
    k_softmax<<<B_ * NH_, 256>>>(p_sc, S_, nullptr);
    k_ctx<<<dim3(H_/128, B_), 256>>>(p_sc, enc, (long long)S_ * H_,
                                     p_ctx, S_, nullptr);
    k_gemm<<<dim3(1, NH_), 256>>>(p_ctx, NH_*H_, (long long)H_,
                                  cavw, H_, (long long)HD_*H_,
                                  cavb, HD_,
                                  p_cao, H_, (long long)HD_,
                                  HD_, H_, 0);

    // ---- LSTM gates: x=[emb, ca] @ wih^T + h @ whh^T (biases in elementwise) ----
    k_gemm<<<dim3(4*H_/64, 1), 256>>>(p_emb, H_, 0, wih,        2*H_, 0, nullptr, 0,
                                      p_gate, 4*H_, 0, 4*H_, H_, 0);
    k_gemm<<<dim3(4*H_/64, 1), 256>>>(p_cao, H_, 0, wih + H_,   2*H_, 0, nullptr, 0,
                                      p_gate, 4*H_, 0, 4*H_, H_, 1);
    k_gemm<<<dim3(4*H_/64, 1), 256>>>(h_in,  H_, 0, whh,        H_,   0, nullptr, 0,
                                      p_gate, 4*H_, 0, 4*H_, H_, 1);

    // ---- LSTM elementwise -> h_new, c_new into d_out ----
    k_lstm<<<(B_*H_ + 255)/256, 256>>>(p_gate, bih, bhh, c_in, out);

    // ---- logits = h_new @ fc_w^T + fc_b ----
    k_gemm<<<dim3((V_ + 63)/64, 1), 256>>>(p_hnew, H_, 0, fcw, H_, 0, fcb, 0,
                                           out, V_, 0, V_, H_, 0);
}

// round 3
// speedup vs baseline: 1.0029x; 1.0029x over previous
#include <cuda_runtime.h>
#include <math.h>

// Problem constants
#define B_    64
#define S_    2048
#define H_    1024
#define NH_   16
#define HD_   64
#define V_    50257
#define MAXLEN_ 1024
#define SLD_  2048            // scores leading dim (max context)
#define SCALE_ 0.125f         // HD^-0.5

// ---------------- scratch (module-load allocated, not runtime alloc) ----------
#define OF_EMB   ((size_t)0)
#define OF_Q     (OF_EMB  + (size_t)B_*H_)
#define OF_QT    (OF_Q    + (size_t)B_*H_)
#define OF_QC    (OF_QT   + (size_t)B_*NH_*H_)
#define OF_SC    (OF_QC   + (size_t)1024)
#define OF_CTX   (OF_SC   + (size_t)B_*NH_*SLD_)
#define OF_SAO   (OF_CTX  + (size_t)B_*NH_*H_)
#define OF_CAO   (OF_SAO  + (size_t)B_*H_)
#define OF_GATE  (OF_CAO  + (size_t)B_*H_)
#define SCRATCH_ (OF_GATE + (size_t)B_*4*H_)

__device__ float g_scratch[SCRATCH_];

// ---------------- embedding gather ----------------
__global__ void k_gather(const int* __restrict__ tok,
                         const float* __restrict__ table,
                         float* __restrict__ out)
{
    int b = blockIdx.x;
    int t = tok[b];
    const float4* src = (const float4*)(table + (size_t)t * H_);
    float4* dst = (float4*)(out + (size_t)b * H_);
    for (int i = threadIdx.x; i < H_/4; i += blockDim.x) dst[i] = src[i];
}

// ---------------- generic tiled SGEMM: C[64 x N] = A[64 x K] @ B[N x K]^T (+bias) ----
// M fixed at 64. Optional batch dim via grid.y with independent strides.
__global__ void k_gemm(const float* __restrict__ A, int lda, long long sA,
                       const float* __restrict__ Bw, int ldb, long long sB,
                       const float* __restrict__ bias, long long sBias,
                       float* __restrict__ C, int ldc, long long sC,
                       int N, int K, int accum)
{
    int bat = blockIdx.y;
    A  += (size_t)bat * sA;
    Bw += (size_t)bat * sB;
    C  += (size_t)bat * sC;
    if (bias) bias += (size_t)bat * sBias;

    int n0 = blockIdx.x * 64;
    __shared__ float As[32][65];
    __shared__ float Bs[32][65];

    int tid = threadIdx.x;
    int tm = (tid / 16) * 4;
    int tn = (tid % 16) * 4;
    int kk = tid % 32;
    int r  = tid / 32;       // 0..7

    float acc[4][4] = {};

    for (int k0 = 0; k0 < K; k0 += 32) {
#pragma unroll
        for (int p = 0; p < 8; p++) {
            int m = r + p * 8;
            As[kk][m] = A[(size_t)m * lda + k0 + kk];
        }
#pragma unroll
        for (int p = 0; p < 8; p++) {
            int nl = r + p * 8;
            int n = n0 + nl;
            Bs[kk][nl] = (n < N) ? Bw[(size_t)n * ldb + k0 + kk] : 0.f;
        }
        __syncthreads();
#pragma unroll
        for (int q = 0; q < 32; q++) {
            float a0 = As[q][tm+0], a1 = As[q][tm+1], a2 = As[q][tm+2], a3 = As[q][tm+3];
            float b0 = Bs[q][tn+0], b1 = Bs[q][tn+1], b2 = Bs[q][tn+2], b3 = Bs[q][tn+3];
            acc[0][0] += a0*b0; acc[0][1] += a0*b1; acc[0][2] += a0*b2; acc[0][3] += a0*b3;
            acc[1][0] += a1*b0; acc[1][1] += a1*b1; acc[1][2] += a1*b2; acc[1][3] += a1*b3;
            acc[2][0] += a2*b0; acc[2][1] += a2*b1; acc[2][2] += a2*b2; acc[2][3] += a2*b3;
            acc[3][0] += a3*b0; acc[3][1] += a3*b1; acc[3][2] += a3*b2; acc[3][3] += a3*b3;
        }
        __syncthreads();
    }

#pragma unroll
    for (int i = 0; i < 4; i++) {
#pragma unroll
        for (int j = 0; j < 4; j++) {
            int n = n0 + tn + j;
            if (n < N) {
                float v = acc[i][j] + (bias ? bias[n] : 0.f);
                size_t idx = (size_t)(tm + i) * ldc + n;
                if (accum) C[idx] += v; else C[idx] = v;
            }
        }
    }
}

// ---------------- q-tilde fold: qt[b,h,d] = sum_j Q[b,h*64+j] * Wk[h*64+j,d]
//                  qc[b,h]   = sum_j Q[b,h*64+j] * bk[h*64+j]
__global__ void k_qt(const float* __restrict__ Q,
                     const float* __restrict__ Wk,
                     const float* __restrict__ bk,
                     float* __restrict__ qt,
                     float* __restrict__ qc)
{
    int h = blockIdx.y;
    int d = blockIdx.x * 64 + (threadIdx.x % 64);
    int bg = threadIdx.x / 64;      // 0..3, each owns 16 batches

    __shared__ float Qs[64][65];
    for (int i = threadIdx.x; i < 64*64; i += 256) {
        int b = i / 64, j = i % 64;
        Qs[b][j] = Q[(size_t)b * H_ + h * 64 + j];
    }
    __syncthreads();

    float acc[16] = {};
#pragma unroll 4
    for (int j = 0; j < 64; j++) {
        float w = Wk[(size_t)(h * 64 + j) * H_ + d];
#pragma unroll
        for (int bb = 0; bb < 16; bb++) acc[bb] += Qs[bg*16 + bb][j] * w;
    }
#pragma unroll
    for (int bb = 0; bb < 16; bb++) {
        int b = bg * 16 + bb;
        qt[((size_t)b * NH_ + h) * H_ + d] = acc[bb];
    }
    if (blockIdx.x == 0 && threadIdx.x < 64) {
        int b = threadIdx.x;
        float s = 0.f;
        for (int j = 0; j < 64; j++) s += Qs[b][j] * bk[h * 64 + j];
        qc[b * NH_ + h] = s;
    }
}

// ---------------- scores[b,h,k] = (qt[b,h,:] . keys[b,k,:] + qc[b,h]) * SCALE, k < L
__global__ void k_scores(const float* __restrict__ qt,
                         const float* __restrict__ qc,
                         const float* __restrict__ keys, long long kbstride,
                         float* __restrict__ scores,
                         int Lmax, const int* __restrict__ Lptr)
{
    int b = blockIdx.y;
    int L = Lptr ? Lptr[0] : Lmax;
    int k0 = blockIdx.x * 32;
    if (k0 >= L) return;

    __shared__ float qs[16][65];
    __shared__ float ks[32][65];

    int tid = threadIdx.x;
    int kl = tid % 32;
    int hg = tid / 32;          // 0..7; owns heads hg and hg+8
    float acc0 = 0.f, acc1 = 0.f;
    const float* kb = keys + (size_t)b * kbstride;

    for (int d0 = 0; d0 < H_; d0 += 64) {
        for (int i = tid; i < 16*64; i += 256) {
            int h = i / 64, dd = i % 64;
            qs[h][dd] = qt[((size_t)b * NH_ + h) * H_ + d0 + dd];
        }
        for (int i = tid; i < 32*16; i += 256) {
            int rr = i / 16, dq = i % 16;
            float4 v = *(const float4*)&kb[(size_t)(k0 + rr) * H_ + d0 + dq * 4];
            ks[rr][dq*4+0] = v.x; ks[rr][dq*4+1] = v.y;
            ks[rr][dq*4+2] = v.z; ks[rr][dq*4+3] = v.w;
        }
        __syncthreads();
#pragma unroll
        for (int dd = 0; dd < 64; dd++) {
            float kv = ks[kl][dd];
            acc0 += qs[hg    ][dd] * kv;
            acc1 += qs[hg + 8][dd] * kv;
        }
        __syncthreads();
    }

    int k = k0 + kl;
    if (k < L) {
        scores[((size_t)b * NH_ + hg    ) * SLD_ + k] = (acc0 + qc[b*NH_ + hg    ]) * SCALE_;
        scores[((size_t)b * NH_ + hg + 8) * SLD_ + k] = (acc1 + qc[b*NH_ + hg + 8]) * SCALE_;
    }
}

// ---------------- softmax over k < L, row = (b*NH+h)
__global__ void k_softmax(float* __restrict__ scores,
                          int Lmax, const int* __restrict__ Lptr)
{
    int L = Lptr ? Lptr[0] : Lmax;
    float* s = scores + (size_t)blockIdx.x * SLD_;
    int tid = threadIdx.x;

    float v[8];
    float mx = -1e30f;
#pragma unroll
    for (int i = 0; i < 8; i++) {
        int k = tid + i * 256;
        v[i] = (k < L) ? s[k] : -1e30f;
        mx = fmaxf(mx, v[i]);
    }
    __shared__ float red[256];
    red[tid] = mx; __syncthreads();
    for (int off = 128; off; off >>= 1) {
        if (tid < off) red[tid] = fmaxf(red[tid], red[tid + off]);
        __syncthreads();
    }
    mx = red[0]; __syncthreads();

    float sum = 0.f;
#pragma unroll
    for (int i = 0; i < 8; i++) { v[i] = __expf(v[i] - mx); sum += v[i]; }
    red[tid] = sum; __syncthreads();
    for (int off = 128; off; off >>= 1) {
        if (tid < off) red[tid] += red[tid + off];
        __syncthreads();
    }
    float inv = 1.f / red[0];
#pragma unroll
    for (int i = 0; i < 8; i++) {
        int k = tid + i * 256;
        if (k < L) s[k] = v[i] * inv;
    }
}

// ---------------- ctx[b,h,d] = sum_{k<L} w[b,h,k] * keys[b,k,d]
__global__ void k_ctx(const float* __restrict__ w,
                      const float* __restrict__ keys, long long kbstride,
                      float* __restrict__ ctx,
                      int Lmax, const int* __restrict__ Lptr)
{
    int b = blockIdx.y;
    int d0 = blockIdx.x * 128;
    int L = Lptr ? Lptr[0] : Lmax;
    int tid = threadIdx.x;
    int dl = tid % 128;
    int hg = tid / 128;          // 0/1 -> heads hg*8 .. hg*8+7

    __shared__ float ws[16][33];
    __shared__ float ks[32][128];

    const float* kb = keys + (size_t)b * kbstride;
    float acc[8] = {};

    for (int k0 = 0; k0 < L; k0 += 32) {
        for (int i = tid; i < 16*32; i += 256) {
            int h = i / 32, kk = i % 32;
            int k = k0 + kk;
            ws[h][kk] = (k < L) ? w[((size_t)b * NH_ + h) * SLD_ + k] : 0.f;
        }
        for (int i = tid; i < 32*32; i += 256) {
            int rr = i / 32, dq = i % 32;
            float4 v = *(const float4*)&kb[(size_t)(k0 + rr) * H_ + d0 + dq * 4];
            ((float4*)&ks[rr][0])[dq] = v;
        }
        __syncthreads();
#pragma unroll
        for (int kk = 0; kk < 32; kk++) {
            float kv = ks[kk][dl];
#pragma unroll
            for (int hh = 0; hh < 8; hh++) acc[hh] += ws[hg*8 + hh][kk] * kv;
        }
        __syncthreads();
    }
#pragma unroll
    for (int hh = 0; hh < 8; hh++) {
        int h = hg * 8 + hh;
        ctx[((size_t)b * NH_ + h) * H_ + d0 + dl] = acc[hh];
    }
}

// ---------------- LSTM elementwise ----------------
__device__ __forceinline__ float sigm(float x) { return 1.f / (1.f + __expf(-x)); }

__global__ void k_lstm(const float* __restrict__ gates,
                       const float* __restrict__ bih,
                       const float* __restrict__ bhh,
                       const float* __restrict__ c_in,
                       float* __restrict__ out)
{
    int idx = blockIdx.x * 256 + threadIdx.x;
    if (idx >= B_ * H_) return;
    int b = idx / H_, o = idx % H_;
    const float* g = gates + (size_t)b * 4 * H_;

    float ig = sigm (g[0*H_ + o] + bih[0*H_ + o] + bhh[0*H_ + o]);
    float fg = sigm (g[1*H_ + o] + bih[1*H_ + o] + bhh[1*H_ + o]);
    float gg = tanhf(g[2*H_ + o] + bih[2*H_ + o] + bhh[2*H_ + o]);
    float og = sigm (g[3*H_ + o] + bih[3*H_ + o] + bhh[3*H_ + o]);

    float c = fg * c_in[idx] + ig * gg;
    float h = og * tanhf(c);

    out[(size_t)B_ * V_ + idx] = h;                       // h_new
    out[(size_t)B_ * V_ + (size_t)B_ * H_ + idx] = c;     // c_new
}

// ---------------- launcher ----------------
extern "C" void kernel_launch(void* const* d_in, const int* in_sizes, int n_in,
                              void* d_out, int out_size)
{
    const int*   tok   = (const int*)  d_in[0];
    const float* enc   = (const float*)d_in[1];
    const float* h_in  = (const float*)d_in[2];
    const float* c_in  = (const float*)d_in[3];
    const float* cache = (const float*)d_in[4];
    const int*   stepp = (const int*)  d_in[5];
    const float* table = (const float*)d_in[6];
    const float* saqw = (const float*)d_in[7];
    const float* saqb = (const float*)d_in[8];
    const float* sakw = (const float*)d_in[9];
    const float* sakb = (const float*)d_in[10];
    const float* savw = (const float*)d_in[11];
    const float* savb = (const float*)d_in[12];
    const float* caqw = (const float*)d_in[13];
    const float* caqb = (const float*)d_in[14];
    const float* cakw = (const float*)d_in[15];
    const float* cakb = (const float*)d_in[16];
    const float* cavw = (const float*)d_in[17];
    const float* cavb = (const float*)d_in[18];
    const float* wih  = (const float*)d_in[19];
    const float* bih  = (const float*)d_in[20];
    const float* whh  = (const float*)d_in[21];
    const float* bhh  = (const float*)d_in[22];
    const float* fcw  = (const float*)d_in[23];
    const float* fcb  = (const float*)d_in[24];
    float* out = (float*)d_out;

    float* sb = nullptr;
    cudaGetSymbolAddress((void**)&sb, g_scratch);

    float* p_emb  = sb + OF_EMB;
    float* p_Q    = sb + OF_Q;
    float* p_qt   = sb + OF_QT;
    float* p_qc   = sb + OF_QC;
    float* p_sc   = sb + OF_SC;
    float* p_ctx  = sb + OF_CTX;
    float* p_sao  = sb + OF_SAO;
    float* p_cao  = sb + OF_CAO;
    float* p_gate = sb + OF_GATE;
    float* p_hnew = out + (size_t)B_ * V_;

    // 1. embedding gather
    k_gather<<<B_, 256>>>(tok, table, p_emb);

    // ---- self-attention (keys/values = kv_cache[:, :step]) ----
    // Q_sa = emb @ sa_q_w^T + b
    k_gemm<<<dim3(H_/64, 1), 256>>>(p_emb, H_, 0, saqw, H_, 0, saqb, 0,
                                    p_Q, H_, 0, H_, H_, 0);
    k_qt<<<dim3(H_/64, NH_), 256>>>(p_Q, sakw, sakb, p_qt, p_qc);
    k_scores<<<dim3(MAXLEN_/32, B_), 256>>>(p_qt, p_qc, cache,
                                            (long long)MAXLEN_ * H_,
                                            p_sc, MAXLEN_, stepp);
    k_softmax<<<B_ * NH_, 256>>>(p_sc, MAXLEN_, stepp);
    k_ctx<<<dim3(H_/128, B_), 256>>>(p_sc, cache, (long long)MAXLEN_ * H_,
                                     p_ctx, MAXLEN_, stepp);
    // per-head V projection: batched over heads via grid.y
    k_gemm<<<dim3(1, NH_), 256>>>(p_ctx, NH_*H_, (long long)H_,
                                  savw, H_, (long long)HD_*H_,
                                  savb, HD_,
                                  p_sao, H_, (long long)HD_,
                                  HD_, H_, 0);

    // ---- cross-attention (keys/values = encoder_outputs) ----
    k_gemm<<<dim3(H_/64, 1), 256>>>(p_sao, H_, 0, caqw, H_, 0, caqb, 0,
                                    p_Q, H_, 0, H_, H_, 0);
    k_qt<<<dim3(H_/64, NH_), 256>>>(p_Q, cakw, cakb, p_qt, p_qc);
    k_scores<<<dim3(S_/32, B_), 256>>>(p_qt, p_qc, enc,
                                       (long long)S_ * H_,
                                       p_sc, S_, nullptr);
    k_softmax<<<B_ * NH_, 256>>>(p_sc, S_, nullptr);
    k_ctx<<<dim3(H_/128, B_), 256>>>(p_sc, enc, (long long)S_ * H_,
                                     p_ctx, S_, nullptr);
    k_gemm<<<dim3(1, NH_), 256>>>(p_ctx, NH_*H_, (long long)H_,
                                  cavw, H_, (long long)HD_*H_,
                                  cavb, HD_,
                                  p_cao, H_, (long long)HD_,
                                  HD_, H_, 0);

    // ---- LSTM gates: x=[emb, ca] @ wih^T + h @ whh^T (biases in elementwise) ----
    k_gemm<<<dim3(4*H_/64, 1), 256>>>(p_emb, H_, 0, wih,        2*H_, 0, nullptr, 0,
                                      p_gate, 4*H_, 0, 4*H_, H_, 0);
    k_gemm<<<dim3(4*H_/64, 1), 256>>>(p_cao, H_, 0, wih + H_,   2*H_, 0, nullptr, 0,
                                      p_gate, 4*H_, 0, 4*H_, H_, 1);
    k_gemm<<<dim3(4*H_/64, 1), 256>>>(h_in,  H_, 0, whh,        H_,   0, nullptr, 0,
                                      p_gate, 4*H_, 0, 4*H_, H_, 1);

    // ---- LSTM elementwise -> h_new, c_new into d_out ----
    k_lstm<<<(B_*H_ + 255)/256, 256>>>(p_gate, bih, bhh, c_in, out);

    // ---- logits = h_new @ fc_w^T + fc_b ----
    k_gemm<<<dim3((V_ + 63)/64, 1), 256>>>(p_hnew, H_, 0, fcw, H_, 0, fcb, 0,
                                           out, V_, 0, V_, H_, 0);
}

// round 4
// speedup vs baseline: 1.0042x; 1.0013x over previous
#include <cuda_runtime.h>
#include <math.h>

// Problem constants
#define B_    64
#define S_    2048
#define H_    1024
#define NH_   16
#define HD_   64
#define V_    50257
#define MAXLEN_ 1024
#define SLD_  2048
#define SCALE_ 0.125f

typedef unsigned long long u64;

__device__ __forceinline__ u64 pk2(float a, float b) {
    u64 r; asm("mov.b64 %0,{%1,%2};" : "=l"(r) : "f"(a), "f"(b)); return r;
}
__device__ __forceinline__ u64 dup2f(float a) { return pk2(a, a); }
__device__ __forceinline__ void fma2(u64& d, u64 a, u64 b) {
    asm("fma.rn.f32x2 %0,%1,%2,%0;" : "+l"(d) : "l"(a), "l"(b));
}
__device__ __forceinline__ void upk2(float& x, float& y, u64 v) {
    asm("mov.b64 {%0,%1},%2;" : "=f"(x), "=f"(y) : "l"(v));
}

// ---------------- scratch ----------
#define OF_EMB   ((size_t)0)
#define OF_Q     (OF_EMB  + (size_t)B_*H_)
#define OF_QT    (OF_Q    + (size_t)B_*H_)
#define OF_QC    (OF_QT   + (size_t)B_*NH_*H_)
#define OF_SC    (OF_QC   + (size_t)1024)
#define OF_CTX   (OF_SC   + (size_t)B_*NH_*SLD_)
#define OF_SAO   (OF_CTX  + (size_t)B_*NH_*H_)
#define OF_CAO   (OF_SAO  + (size_t)B_*H_)
#define OF_GATE  (OF_CAO  + (size_t)B_*H_)
#define SCRATCH_ (OF_GATE + (size_t)B_*4*H_)

__device__ float g_scratch[SCRATCH_];

// ---------------- embedding gather ----------------
__global__ void k_gather(const int* __restrict__ tok,
                         const float* __restrict__ table,
                         float* __restrict__ out)
{
    int b = blockIdx.x;
    int t = tok[b];
    const float4* src = (const float4*)(table + (size_t)t * H_);
    float4* dst = (float4*)(out + (size_t)b * H_);
    for (int i = threadIdx.x; i < H_/4; i += blockDim.x) dst[i] = src[i];
}

// ---------------- SGEMM v2: C[64 x N] = A[64 x K] @ B[N x K]^T (+bias) -------
// 256 threads, block tile 64m x 128n, K-step 32, thread tile 4m x 8n, f32x2.
__global__ __launch_bounds__(256) void k_gemm2(
        const float* __restrict__ A, int lda, long long sA,
        const float* __restrict__ Bw, int ldb, long long sB,
        const float* __restrict__ bias, long long sBias,
        float* __restrict__ C, int ldc, long long sC,
        int N, int K, int accum)
{
    int bat = blockIdx.y;
    A  += (size_t)bat * sA;
    Bw += (size_t)bat * sB;
    C  += (size_t)bat * sC;
    if (bias) bias += (size_t)bat * sBias;

    __shared__ float As[32 * 68];
    __shared__ float Bs[32 * 132];

    int t  = threadIdx.x;
    int n0 = blockIdx.x * 128;
    int tm = (t / 16) * 4;
    int tn = (t % 16) * 8;

    int lr = t / 8;            // 0..31
    int k4 = (t % 8) * 4;      // 0,4,...,28

    u64 acc2[4][4];
#pragma unroll
    for (int i = 0; i < 4; i++)
#pragma unroll
        for (int j = 0; j < 4; j++) acc2[i][j] = 0ULL;

    for (int k0 = 0; k0 < K; k0 += 32) {
        // load A 64x32 (transpose into As[k][m])
#pragma unroll
        for (int p = 0; p < 2; p++) {
            int m = lr + p * 32;
            float4 av = *(const float4*)&A[(size_t)m * lda + k0 + k4];
            As[(k4+0)*68 + m] = av.x;
            As[(k4+1)*68 + m] = av.y;
            As[(k4+2)*68 + m] = av.z;
            As[(k4+3)*68 + m] = av.w;
        }
        // load B 128x32 (transpose into Bs[k][n])
#pragma unroll
        for (int p = 0; p < 4; p++) {
            int n = lr + p * 32;
            int gn = n0 + n;
            float4 bv = make_float4(0.f, 0.f, 0.f, 0.f);
            if (gn < N) bv = *(const float4*)&Bw[(size_t)gn * ldb + k0 + k4];
            Bs[(k4+0)*132 + n] = bv.x;
            Bs[(k4+1)*132 + n] = bv.y;
            Bs[(k4+2)*132 + n] = bv.z;
            Bs[(k4+3)*132 + n] = bv.w;
        }
        __syncthreads();

#pragma unroll 4
        for (int kk = 0; kk < 32; kk++) {
            float4 a = *(const float4*)&As[kk*68 + tm];
            ulonglong2 b01 = *(const ulonglong2*)&Bs[kk*132 + tn];
            ulonglong2 b23 = *(const ulonglong2*)&Bs[kk*132 + tn + 4];
            u64 ad0 = dup2f(a.x), ad1 = dup2f(a.y), ad2 = dup2f(a.z), ad3 = dup2f(a.w);
            fma2(acc2[0][0], ad0, b01.x); fma2(acc2[0][1], ad0, b01.y);
            fma2(acc2[0][2], ad0, b23.x); fma2(acc2[0][3], ad0, b23.y);
            fma2(acc2[1][0], ad1, b01.x); fma2(acc2[1][1], ad1, b01.y);
            fma2(acc2[1][2], ad1, b23.x); fma2(acc2[1][3], ad1, b23.y);
            fma2(acc2[2][0], ad2, b01.x); fma2(acc2[2][1], ad2, b01.y);
            fma2(acc2[2][2], ad2, b23.x); fma2(acc2[2][3], ad2, b23.y);
            fma2(acc2[3][0], ad3, b01.x); fma2(acc2[3][1], ad3, b01.y);
            fma2(acc2[3][2], ad3, b23.x); fma2(acc2[3][3], ad3, b23.y);
        }
        __syncthreads();
    }

#pragma unroll
    for (int mi = 0; mi < 4; mi++) {
#pragma unroll
        for (int np = 0; np < 4; np++) {
            float c0, c1;
            upk2(c0, c1, acc2[mi][np]);
            int n = n0 + tn + np * 2;
            size_t base = (size_t)(tm + mi) * ldc;
            if (n < N) {
                float v = c0 + (bias ? bias[n] : 0.f);
                if (accum) C[base + n] += v; else C[base + n] = v;
            }
            if (n + 1 < N) {
                float v = c1 + (bias ? bias[n+1] : 0.f);
                if (accum) C[base + n + 1] += v; else C[base + n + 1] = v;
            }
        }
    }
}

// ---------------- q-tilde fold, TRANSPOSED output: qtT[b][d][h] ----------
__global__ void k_qt(const float* __restrict__ Q,
                     const float* __restrict__ Wk,
                     const float* __restrict__ bk,
                     float* __restrict__ qtT,
                     float* __restrict__ qc)
{
    int h = blockIdx.y;
    int d = blockIdx.x * 64 + (threadIdx.x % 64);
    int bg = threadIdx.x / 64;

    __shared__ float Qs[64][65];
    for (int i = threadIdx.x; i < 64*64; i += 256) {
        int b = i / 64, j = i % 64;
        Qs[b][j] = Q[(size_t)b * H_ + h * 64 + j];
    }
    __syncthreads();

    float acc[16] = {};
#pragma unroll 4
    for (int j = 0; j < 64; j++) {
        float w = Wk[(size_t)(h * 64 + j) * H_ + d];
#pragma unroll
        for (int bb = 0; bb < 16; bb++) acc[bb] += Qs[bg*16 + bb][j] * w;
    }
#pragma unroll
    for (int bb = 0; bb < 16; bb++) {
        int b = bg * 16 + bb;
        qtT[((size_t)b * H_ + d) * NH_ + h] = acc[bb];
    }
    if (blockIdx.x == 0 && threadIdx.x < 64) {
        int b = threadIdx.x;
        float s = 0.f;
        for (int j = 0; j < 64; j++) s += Qs[b][j] * bk[h * 64 + j];
        qc[b * NH_ + h] = s;
    }
}

// ---------------- scores v2 --------------------------------------------------
// block: (batch b, key tile of 256).  128 threads; thread owns keys t and t+128
// for ALL 16 heads, accumulating in 8 h-pair f32x2 accumulators per key.
__global__ __launch_bounds__(128) void k_scores(
        const float* __restrict__ qtT,
        const float* __restrict__ qc,
        const float* __restrict__ keys, long long kbstride,
        float* __restrict__ scores,
        int Lmax, const int* __restrict__ Lptr)
{
    int b  = blockIdx.y;
    int L  = Lptr ? Lptr[0] : Lmax;
    int k0 = blockIdx.x * 256;
    if (k0 >= L) return;

    __shared__ float ks[256 * 33];
    __shared__ float qsT[32 * 16];

    int t = threadIdx.x;
    const float* kb = keys + (size_t)b * kbstride;
    const float* qb = qtT + (size_t)b * H_ * NH_;

    u64 acc[8][2];
#pragma unroll
    for (int i = 0; i < 8; i++) { acc[i][0] = 0ULL; acc[i][1] = 0ULL; }

    int klr = t >> 3;          // 0..15 base key row
    int d4  = (t & 7) * 4;     // 0,4,...,28

    for (int d0 = 0; d0 < H_; d0 += 32) {
        // load q chunk: 32 x 16, contiguous
        ((float4*)qsT)[t] = ((const float4*)(qb + (size_t)d0 * NH_))[t];
        // load key slab: 256 rows x 32 d, scalar-stride-33 (conflict-free)
#pragma unroll
        for (int p = 0; p < 16; p++) {
            int k = klr + p * 16;
            float4 v = *(const float4*)&kb[(size_t)(k0 + k) * H_ + d0 + d4];
            ks[k*33 + d4 + 0] = v.x;
            ks[k*33 + d4 + 1] = v.y;
            ks[k*33 + d4 + 2] = v.z;
            ks[k*33 + d4 + 3] = v.w;
        }
        __syncthreads();

#pragma unroll 4
        for (int dd = 0; dd < 32; dd++) {
            u64 kd0 = dup2f(ks[t*33 + dd]);
            u64 kd1 = dup2f(ks[(t+128)*33 + dd]);
            const u64* qp = (const u64*)&qsT[dd * 16];
#pragma unroll
            for (int hp = 0; hp < 8; hp++) {
                u64 q2 = qp[hp];
                fma2(acc[hp][0], q2, kd0);
                fma2(acc[hp][1], q2, kd1);
            }
        }
        __syncthreads();
    }

    int kA = k0 + t, kB = k0 + t + 128;
#pragma unroll
    for (int hp = 0; hp < 8; hp++) {
        float s0, s1, s2, s3;
        upk2(s0, s1, acc[hp][0]);   // key kA, heads 2hp, 2hp+1
        upk2(s2, s3, acc[hp][1]);   // key kB
        int h0 = 2*hp, h1 = 2*hp + 1;
        float c0 = qc[b*NH_ + h0], c1 = qc[b*NH_ + h1];
        if (kA < L) {
            scores[((size_t)b*NH_ + h0)*SLD_ + kA] = (s0 + c0) * SCALE_;
            scores[((size_t)b*NH_ + h1)*SLD_ + kA] = (s1 + c1) * SCALE_;
        }
        if (kB < L) {
            scores[((size_t)b*NH_ + h0)*SLD_ + kB] = (s2 + c0) * SCALE_;
            scores[((size_t)b*NH_ + h1)*SLD_ + kB] = (s3 + c1) * SCALE_;
        }
    }
}

// ---------------- softmax ----------------
__global__ void k_softmax(float* __restrict__ scores,
                          int Lmax, const int* __restrict__ Lptr)
{
    int L = Lptr ? Lptr[0] : Lmax;
    float* s = scores + (size_t)blockIdx.x * SLD_;
    int tid = threadIdx.x;

    float v[8];
    float mx = -1e30f;
#pragma unroll
    for (int i = 0; i < 8; i++) {
        int k = tid + i * 256;
        v[i] = (k < L) ? s[k] : -1e30f;
        mx = fmaxf(mx, v[i]);
    }
    __shared__ float red[256];
    red[tid] = mx; __syncthreads();
    for (int off = 128; off; off >>= 1) {
        if (tid < off) red[tid] = fmaxf(red[tid], red[tid + off]);
        __syncthreads();
    }
    mx = red[0]; __syncthreads();

    float sum = 0.f;
#pragma unroll
    for (int i = 0; i < 8; i++) { v[i] = __expf(v[i] - mx); sum += v[i]; }
    red[tid] = sum; __syncthreads();
    for (int off = 128; off; off >>= 1) {
        if (tid < off) red[tid] += red[tid + off];
        __syncthreads();
    }
    float inv = 1.f / red[0];
#pragma unroll
    for (int i = 0; i < 8; i++) {
        int k = tid + i * 256;
        if (k < L) s[k] = v[i] * inv;
    }
}

// ---------------- ctx v2 -----------------------------------------------------
// block: (d-chunk 256, batch b). 128 threads; thread owns d = d0+t, d0+t+128
// for ALL 16 heads.  ctx[b,h,d] = sum_{k<L} w[b,h,k] * keys[b,k,d]
__global__ __launch_bounds__(128) void k_ctx(
        const float* __restrict__ w,
        const float* __restrict__ keys, long long kbstride,
        float* __restrict__ ctx,
        int Lmax, const int* __restrict__ Lptr)
{
    int b  = blockIdx.y;
    int d0 = blockIdx.x * 256;
    int L  = Lptr ? Lptr[0] : Lmax;
    int t  = threadIdx.x;

    __shared__ float es[32 * 256];
    __shared__ float ws[32 * 18];

    const float* kb = keys + (size_t)b * kbstride;

    u64 acc[8][2];
#pragma unroll
    for (int i = 0; i < 8; i++) { acc[i][0] = 0ULL; acc[i][1] = 0ULL; }

    int klr = t >> 6;          // 0..1
    int d4  = (t & 63) * 4;    // 0..252

    for (int k0 = 0; k0 < L; k0 += 32) {
        // w tile transposed: ws[kk][h], stride 18
#pragma unroll
        for (int p = 0; p < 4; p++) {
            int idx = t + p * 128;
            int h = idx / 32, kk = idx % 32;
            int k = k0 + kk;
            ws[kk*18 + h] = (k < L) ? w[((size_t)b*NH_ + h)*SLD_ + k] : 0.f;
        }
        // enc tile: es[kk][d], row-major
#pragma unroll
        for (int p = 0; p < 16; p++) {
            int kk = klr + p * 2;
            float4 v = *(const float4*)&kb[(size_t)(k0 + kk) * H_ + d0 + d4];
            *(float4*)&es[kk*256 + d4] = v;
        }
        __syncthreads();

#pragma unroll 4
        for (int kk = 0; kk < 32; kk++) {
            u64 e0 = dup2f(es[kk*256 + t]);
            u64 e1 = dup2f(es[kk*256 + t + 128]);
            const u64* wp = (const u64*)&ws[kk*18];
#pragma unroll
            for (int hp = 0; hp < 8; hp++) {
                u64 w2 = wp[hp];
                fma2(acc[hp][0], w2, e0);
                fma2(acc[hp][1], w2, e1);
            }
        }
        __syncthreads();
    }

    int dA = d0 + t, dB = d0 + t + 128;
#pragma unroll
    for (int hp = 0; hp < 8; hp++) {
        float c0, c1, c2, c3;
        upk2(c0, c1, acc[hp][0]);
        upk2(c2, c3, acc[hp][1]);
        int h0 = 2*hp, h1 = 2*hp + 1;
        ctx[((size_t)b*NH_ + h0)*H_ + dA] = c0;
        ctx[((size_t)b*NH_ + h1)*H_ + dA] = c1;
        ctx[((size_t)b*NH_ + h0)*H_ + dB] = c2;
        ctx[((size_t)b*NH_ + h1)*H_ + dB] = c3;
    }
}

// ---------------- LSTM elementwise ----------------
__device__ __forceinline__ float sigm(float x) { return 1.f / (1.f + __expf(-x)); }

__global__ void k_lstm(const float* __restrict__ gates,
                       const float* __restrict__ bih,
                       const float* __restrict__ bhh,
                       const float* __restrict__ c_in,
                       float* __restrict__ out)
{
    int idx = blockIdx.x * 256 + threadIdx.x;
    if (idx >= B_ * H_) return;
    int b = idx / H_, o = idx % H_;
    const float* g = gates + (size_t)b * 4 * H_;

    float ig = sigm (g[0*H_ + o] + bih[0*H_ + o] + bhh[0*H_ + o]);
    float fg = sigm (g[1*H_ + o] + bih[1*H_ + o] + bhh[1*H_ + o]);
    float gg = tanhf(g[2*H_ + o] + bih[2*H_ + o] + bhh[2*H_ + o]);
    float og = sigm (g[3*H_ + o] + bih[3*H_ + o] + bhh[3*H_ + o]);

    float c = fg * c_in[idx] + ig * gg;
    float h = og * tanhf(c);

    out[(size_t)B_ * V_ + idx] = h;
    out[(size_t)B_ * V_ + (size_t)B_ * H_ + idx] = c;
}

// ---------------- launcher ----------------
extern "C" void kernel_launch(void* const* d_in, const int* in_sizes, int n_in,
                              void* d_out, int out_size)
{
    const int*   tok   = (const int*)  d_in[0];
    const float* enc   = (const float*)d_in[1];
    const float* h_in  = (const float*)d_in[2];
    const float* c_in  = (const float*)d_in[3];
    const float* cache = (const float*)d_in[4];
    const int*   stepp = (const int*)  d_in[5];
    const float* table = (const float*)d_in[6];
    const float* saqw = (const float*)d_in[7];
    const float* saqb = (const float*)d_in[8];
    const float* sakw = (const float*)d_in[9];
    const float* sakb = (const float*)d_in[10];
    const float* savw = (const float*)d_in[11];
    const float* savb = (const float*)d_in[12];
    const float* caqw = (const float*)d_in[13];
    const float* caqb = (const float*)d_in[14];
    const float* cakw = (const float*)d_in[15];
    const float* cakb = (const float*)d_in[16];
    const float* cavw = (const float*)d_in[17];
    const float* cavb = (const float*)d_in[18];
    const float* wih  = (const float*)d_in[19];
    const float* bih  = (const float*)d_in[20];
    const float* whh  = (const float*)d_in[21];
    const float* bhh  = (const float*)d_in[22];
    const float* fcw  = (const float*)d_in[23];
    const float* fcb  = (const float*)d_in[24];
    float* out = (float*)d_out;

    float* sb = nullptr;
    cudaGetSymbolAddress((void**)&sb, g_scratch);

    float* p_emb  = sb + OF_EMB;
    float* p_Q    = sb + OF_Q;
    float* p_qt   = sb + OF_QT;
    float* p_qc   = sb + OF_QC;
    float* p_sc   = sb + OF_SC;
    float* p_ctx  = sb + OF_CTX;
    float* p_sao  = sb + OF_SAO;
    float* p_cao  = sb + OF_CAO;
    float* p_gate = sb + OF_GATE;
    float* p_hnew = out + (size_t)B_ * V_;

    // 1. embedding gather
    k_gather<<<B_, 256>>>(tok, table, p_emb);

    // ---- self-attention (keys/values = kv_cache[:, :step]) ----
    k_gemm2<<<dim3(H_/128, 1), 256>>>(p_emb, H_, 0, saqw, H_, 0, saqb, 0,
                                      p_Q, H_, 0, H_, H_, 0);
    k_qt<<<dim3(H_/64, NH_), 256>>>(p_Q, sakw, sakb, p_qt, p_qc);
    k_scores<<<dim3(MAXLEN_/256, B_), 128>>>(p_qt, p_qc, cache,
                                             (long long)MAXLEN_ * H_,
                                             p_sc, MAXLEN_, stepp);
    k_softmax<<<B_ * NH_, 256>>>(p_sc, MAXLEN_, stepp);
    k_ctx<<<dim3(H_/256, B_), 128>>>(p_sc, cache, (long long)MAXLEN_ * H_,
                                     p_ctx, MAXLEN_, stepp);
    k_gemm2<<<dim3(1, NH_), 256>>>(p_ctx, NH_*H_, (long long)H_,
                                   savw, H_, (long long)HD_*H_,
                                   savb, HD_,
                                   p_sao, H_, (long long)HD_,
                                   HD_, H_, 0);

    // ---- cross-attention (keys/values = encoder_outputs) ----
    k_gemm2<<<dim3(H_/128, 1), 256>>>(p_sao, H_, 0, caqw, H_, 0, caqb, 0,
                                      p_Q, H_, 0, H_, H_, 0);
    k_qt<<<dim3(H_/64, NH_), 256>>>(p_Q, cakw, cakb, p_qt, p_qc);
    k_scores<<<dim3(S_/256, B_), 128>>>(p_qt, p_qc, enc,
                                        (long long)S_ * H_,
                                        p_sc, S_, nullptr);
    k_softmax<<<B_ * NH_, 256>>>(p_sc, S_, nullptr);
    k_ctx<<<dim3(H_/256, B_), 128>>>(p_sc, enc, (long long)S_ * H_,
                                     p_ctx, S_, nullptr);
    k_gemm2<<<dim3(1, NH_), 256>>>(p_ctx, NH_*H_, (long long)H_,
                                   cavw, H_, (long long)HD_*H_,
                                   cavb, HD_,
                                   p_cao, H_, (long long)HD_,
                                   HD_, H_, 0);

    // ---- LSTM gates ----
    k_gemm2<<<dim3(4*H_/128, 1), 256>>>(p_emb, H_, 0, wih,      2*H_, 0, nullptr, 0,
                                        p_gate, 4*H_, 0, 4*H_, H_, 0);
    k_gemm2<<<dim3(4*H_/128, 1), 256>>>(p_cao, H_, 0, wih + H_, 2*H_, 0, nullptr, 0,
                                        p_gate, 4*H_, 0, 4*H_, H_, 1);
    k_gemm2<<<dim3(4*H_/128, 1), 256>>>(h_in,  H_, 0, whh,      H_,   0, nullptr, 0,
                                        p_gate, 4*H_, 0, 4*H_, H_, 1);

    // ---- LSTM elementwise ----
    k_lstm<<<(B_*H_ + 255)/256, 256>>>(p_gate, bih, bhh, c_in, out);

    // ---- logits = h_new @ fc_w^T + fc_b ----
    k_gemm2<<<dim3((V_ + 127)/128, 1), 256>>>(p_hnew, H_, 0, fcw, H_, 0, fcb, 0,
                                              out, V_, 0, V_, H_, 0);
}

// round 5
// speedup vs baseline: 1.2724x; 1.2671x over previous
#include <cuda_runtime.h>
#include <math.h>

// Problem constants
#define B_    64
#define S_    2048
#define H_    1024
#define NH_   16
#define HD_   64
#define V_    50257
#define MAXLEN_ 1024
#define SLD_  2048
#define SCALE_ 0.125f

typedef unsigned long long u64;

__device__ __forceinline__ u64 pk2(float a, float b) {
    u64 r; asm("mov.b64 %0,{%1,%2};" : "=l"(r) : "f"(a), "f"(b)); return r;
}
__device__ __forceinline__ u64 dup2f(float a) { return pk2(a, a); }
__device__ __forceinline__ void fma2(u64& d, u64 a, u64 b) {
    asm("fma.rn.f32x2 %0,%1,%2,%0;" : "+l"(d) : "l"(a), "l"(b));
}
__device__ __forceinline__ void upk2(float& x, float& y, u64 v) {
    asm("mov.b64 {%0,%1},%2;" : "=f"(x), "=f"(y) : "l"(v));
}

// ---------------- scratch ----------
#define OF_EMB   ((size_t)0)
#define OF_Q     (OF_EMB  + (size_t)B_*H_)
#define OF_QT    (OF_Q    + (size_t)B_*H_)
#define OF_QC    (OF_QT   + (size_t)B_*NH_*H_)
#define OF_SC    (OF_QC   + (size_t)1024)
#define OF_CTX   (OF_SC   + (size_t)B_*NH_*SLD_)
#define OF_SAO   (OF_CTX  + (size_t)B_*NH_*H_)
#define OF_CAO   (OF_SAO  + (size_t)B_*H_)
#define OF_GATE  (OF_CAO  + (size_t)B_*H_)
#define SCRATCH_ (OF_GATE + (size_t)B_*4*H_)

__device__ float g_scratch[SCRATCH_];

// ---------------- zero ----------------
__global__ void k_zero(float* __restrict__ p, int n)
{
    int i = blockIdx.x * 1024 + threadIdx.x * 4;
    if (i < n) *(float4*)(p + i) = make_float4(0.f, 0.f, 0.f, 0.f);
}

// ---------------- embedding gather ----------------
__global__ void k_gather(const int* __restrict__ tok,
                         const float* __restrict__ table,
                         float* __restrict__ out)
{
    int b = blockIdx.x;
    int t = tok[b];
    const float4* src = (const float4*)(table + (size_t)t * H_);
    float4* dst = (float4*)(out + (size_t)b * H_);
    for (int i = threadIdx.x; i < H_/4; i += blockDim.x) dst[i] = src[i];
}

// ---------------- SGEMM: C[64 x N] = A[64 x K] @ B[N x K]^T (+bias) ---------
// 256 threads, block tile 64m x 128n, K-step 32, thread tile 4m x 8n, f32x2.
// mode: 0 = write (+bias), 1 = serial accumulate, 2 = atomicAdd into
// pre-zeroed C (bias added only by z-slice 0).  grid.z = K split slices.
__global__ __launch_bounds__(256) void k_gemm2(
        const float* __restrict__ A, int lda, long long sA,
        const float* __restrict__ Bw, int ldb, long long sB,
        const float* __restrict__ bias, long long sBias,
        float* __restrict__ C, int ldc, long long sC,
        int N, int K, int mode)
{
    int bat = blockIdx.y;
    A  += (size_t)bat * sA;
    Bw += (size_t)bat * sB;
    C  += (size_t)bat * sC;
    if (bias) bias += (size_t)bat * sBias;

    int kper = K / gridDim.z;
    int kbeg = blockIdx.z * kper;
    int kend = kbeg + kper;
    bool addb = (bias != nullptr) && (blockIdx.z == 0);

    __shared__ float As[32 * 68];
    __shared__ float Bs[32 * 132];

    int t  = threadIdx.x;
    int n0 = blockIdx.x * 128;
    int tm = (t / 16) * 4;
    int tn = (t % 16) * 8;

    int lr = t / 8;
    int k4 = (t % 8) * 4;

    u64 acc2[4][4];
#pragma unroll
    for (int i = 0; i < 4; i++)
#pragma unroll
        for (int j = 0; j < 4; j++) acc2[i][j] = 0ULL;

    for (int k0 = kbeg; k0 < kend; k0 += 32) {
#pragma unroll
        for (int p = 0; p < 2; p++) {
            int m = lr + p * 32;
            float4 av = *(const float4*)&A[(size_t)m * lda + k0 + k4];
            As[(k4+0)*68 + m] = av.x;
            As[(k4+1)*68 + m] = av.y;
            As[(k4+2)*68 + m] = av.z;
            As[(k4+3)*68 + m] = av.w;
        }
#pragma unroll
        for (int p = 0; p < 4; p++) {
            int n = lr + p * 32;
            int gn = n0 + n;
            float4 bv = make_float4(0.f, 0.f, 0.f, 0.f);
            if (gn < N) bv = *(const float4*)&Bw[(size_t)gn * ldb + k0 + k4];
            Bs[(k4+0)*132 + n] = bv.x;
            Bs[(k4+1)*132 + n] = bv.y;
            Bs[(k4+2)*132 + n] = bv.z;
            Bs[(k4+3)*132 + n] = bv.w;
        }
        __syncthreads();

#pragma unroll 4
        for (int kk = 0; kk < 32; kk++) {
            float4 a = *(const float4*)&As[kk*68 + tm];
            ulonglong2 b01 = *(const ulonglong2*)&Bs[kk*132 + tn];
            ulonglong2 b23 = *(const ulonglong2*)&Bs[kk*132 + tn + 4];
            u64 ad0 = dup2f(a.x), ad1 = dup2f(a.y), ad2 = dup2f(a.z), ad3 = dup2f(a.w);
            fma2(acc2[0][0], ad0, b01.x); fma2(acc2[0][1], ad0, b01.y);
            fma2(acc2[0][2], ad0, b23.x); fma2(acc2[0][3], ad0, b23.y);
            fma2(acc2[1][0], ad1, b01.x); fma2(acc2[1][1], ad1, b01.y);
            fma2(acc2[1][2], ad1, b23.x); fma2(acc2[1][3], ad1, b23.y);
            fma2(acc2[2][0], ad2, b01.x); fma2(acc2[2][1], ad2, b01.y);
            fma2(acc2[2][2], ad2, b23.x); fma2(acc2[2][3], ad2, b23.y);
            fma2(acc2[3][0], ad3, b01.x); fma2(acc2[3][1], ad3, b01.y);
            fma2(acc2[3][2], ad3, b23.x); fma2(acc2[3][3], ad3, b23.y);
        }
        __syncthreads();
    }

#pragma unroll
    for (int mi = 0; mi < 4; mi++) {
#pragma unroll
        for (int np = 0; np < 4; np++) {
            float c0, c1;
            upk2(c0, c1, acc2[mi][np]);
            int n = n0 + tn + np * 2;
            size_t base = (size_t)(tm + mi) * ldc;
#pragma unroll
            for (int q = 0; q < 2; q++) {
                float v = (q == 0) ? c0 : c1;
                int nn = n + q;
                if (nn < N) {
                    if (mode == 2) {
                        if (addb) v += bias[nn];
                        atomicAdd(&C[base + nn], v);
                    } else {
                        if (bias) v += bias[nn];
                        if (mode == 1) C[base + nn] += v;
                        else           C[base + nn]  = v;
                    }
                }
            }
        }
    }
}

// ---------------- q-tilde fold, TRANSPOSED output: qtT[b][d][h] ----------
__global__ void k_qt(const float* __restrict__ Q,
                     const float* __restrict__ Wk,
                     const float* __restrict__ bk,
                     float* __restrict__ qtT,
                     float* __restrict__ qc)
{
    int h = blockIdx.y;
    int d = blockIdx.x * 64 + (threadIdx.x % 64);
    int bg = threadIdx.x / 64;

    __shared__ float Qs[64][65];
    for (int i = threadIdx.x; i < 64*64; i += 256) {
        int b = i / 64, j = i % 64;
        Qs[b][j] = Q[(size_t)b * H_ + h * 64 + j];
    }
    __syncthreads();

    float acc[16] = {};
#pragma unroll 4
    for (int j = 0; j < 64; j++) {
        float w = Wk[(size_t)(h * 64 + j) * H_ + d];
#pragma unroll
        for (int bb = 0; bb < 16; bb++) acc[bb] += Qs[bg*16 + bb][j] * w;
    }
#pragma unroll
    for (int bb = 0; bb < 16; bb++) {
        int b = bg * 16 + bb;
        qtT[((size_t)b * H_ + d) * NH_ + h] = acc[bb];
    }
    if (blockIdx.x == 0 && threadIdx.x < 64) {
        int b = threadIdx.x;
        float s = 0.f;
        for (int j = 0; j < 64; j++) s += Qs[b][j] * bk[h * 64 + j];
        qc[b * NH_ + h] = s;
    }
}

// ---------------- scores v3 --------------------------------------------------
// block = (key tile of 256, batch). 256 threads; thread owns key t for all
// 16 heads (8 f32x2 accumulators).
__global__ __launch_bounds__(256) void k_scores(
        const float* __restrict__ qtT,
        const float* __restrict__ qc,
        const float* __restrict__ keys, long long kbstride,
        float* __restrict__ scores,
        int Lmax, const int* __restrict__ Lptr)
{
    int b  = blockIdx.y;
    int L  = Lptr ? Lptr[0] : Lmax;
    int k0 = blockIdx.x * 256;
    if (k0 >= L) return;

    __shared__ float ks[256 * 33];
    __shared__ float qs[32 * 16];

    int t = threadIdx.x;
    const float* kb = keys + (size_t)b * kbstride;
    const float* qb = qtT + (size_t)b * H_ * NH_;

    u64 acc[8];
#pragma unroll
    for (int i = 0; i < 8; i++) acc[i] = 0ULL;

    int row = t >> 3;           // 0..31
    int d4  = (t & 7) * 4;      // 0..28

    for (int d0 = 0; d0 < H_; d0 += 32) {
        if (t < 128)
            ((float4*)qs)[t] = ((const float4*)(qb + (size_t)d0 * NH_))[t];
#pragma unroll
        for (int p = 0; p < 8; p++) {
            int k = row + p * 32;
            float4 v = *(const float4*)&kb[(size_t)(k0 + k) * H_ + d0 + d4];
            ks[k*33 + d4 + 0] = v.x;
            ks[k*33 + d4 + 1] = v.y;
            ks[k*33 + d4 + 2] = v.z;
            ks[k*33 + d4 + 3] = v.w;
        }
        __syncthreads();

#pragma unroll 4
        for (int dd = 0; dd < 32; dd++) {
            u64 kd = dup2f(ks[t*33 + dd]);
            const u64* qp = (const u64*)&qs[dd * 16];
#pragma unroll
            for (int hp = 0; hp < 8; hp++)
                fma2(acc[hp], qp[hp], kd);
        }
        __syncthreads();
    }

    int k = k0 + t;
    if (k < L) {
#pragma unroll
        for (int hp = 0; hp < 8; hp++) {
            float s0, s1;
            upk2(s0, s1, acc[hp]);
            int h0 = 2*hp, h1 = 2*hp + 1;
            scores[((size_t)b*NH_ + h0)*SLD_ + k] = (s0 + qc[b*NH_ + h0]) * SCALE_;
            scores[((size_t)b*NH_ + h1)*SLD_ + k] = (s1 + qc[b*NH_ + h1]) * SCALE_;
        }
    }
}

// ---------------- softmax ----------------
__global__ void k_softmax(float* __restrict__ scores,
                          int Lmax, const int* __restrict__ Lptr)
{
    int L = Lptr ? Lptr[0] : Lmax;
    float* s = scores + (size_t)blockIdx.x * SLD_;
    int tid = threadIdx.x;

    float v[8];
    float mx = -1e30f;
#pragma unroll
    for (int i = 0; i < 8; i++) {
        int k = tid + i * 256;
        v[i] = (k < L) ? s[k] : -1e30f;
        mx = fmaxf(mx, v[i]);
    }
    __shared__ float red[256];
    red[tid] = mx; __syncthreads();
    for (int off = 128; off; off >>= 1) {
        if (tid < off) red[tid] = fmaxf(red[tid], red[tid + off]);
        __syncthreads();
    }
    mx = red[0]; __syncthreads();

    float sum = 0.f;
#pragma unroll
    for (int i = 0; i < 8; i++) { v[i] = __expf(v[i] - mx); sum += v[i]; }
    red[tid] = sum; __syncthreads();
    for (int off = 128; off; off >>= 1) {
        if (tid < off) red[tid] += red[tid + off];
        __syncthreads();
    }
    float inv = 1.f / red[0];
#pragma unroll
    for (int i = 0; i < 8; i++) {
        int k = tid + i * 256;
        if (k < L) s[k] = v[i] * inv;
    }
}

// ---------------- ctx v3 -----------------------------------------------------
// block = (d-chunk 128, batch). 256 threads; thread owns d = d0 + (t&127),
// head-group hg = t>>7 (8 heads = 4 f32x2 accs).
__global__ __launch_bounds__(256) void k_ctx(
        const float* __restrict__ w,
        const float* __restrict__ keys, long long kbstride,
        float* __restrict__ ctx,
        int Lmax, const int* __restrict__ Lptr)
{
    int b  = blockIdx.y;
    int d0 = blockIdx.x * 128;
    int L  = Lptr ? Lptr[0] : Lmax;
    int t  = threadIdx.x;

    __shared__ float es[32 * 132];
    __shared__ float ws[32 * 18];

    const float* kb = keys + (size_t)b * kbstride + d0;

    u64 acc[4];
#pragma unroll
    for (int i = 0; i < 4; i++) acc[i] = 0ULL;

    int dl = t & 127;
    int hg = t >> 7;

    for (int k0 = 0; k0 < L; k0 += 32) {
        // ws[kk][h] transposed weights, stride 18
#pragma unroll
        for (int p = 0; p < 2; p++) {
            int idx = t + p * 256;
            int h = idx >> 5, kk = idx & 31;
            int k = k0 + kk;
            ws[kk*18 + h] = (k < L) ? w[((size_t)b*NH_ + h)*SLD_ + k] : 0.f;
        }
        // es[kk][d] tile: 32 rows x 128 d
#pragma unroll
        for (int p = 0; p < 4; p++) {
            int kk = (t >> 5) + p * 8;
            float4 v = *(const float4*)&kb[(size_t)(k0 + kk) * H_ + (t & 31) * 4];
            *(float4*)&es[kk*132 + (t & 31) * 4] = v;
        }
        __syncthreads();

#pragma unroll 4
        for (int kk = 0; kk < 32; kk++) {
            u64 e = dup2f(es[kk*132 + dl]);
            const u64* wp = (const u64*)&ws[kk*18 + hg*8];
#pragma unroll
            for (int j = 0; j < 4; j++)
                fma2(acc[j], wp[j], e);
        }
        __syncthreads();
    }

#pragma unroll
    for (int j = 0; j < 4; j++) {
        float c0, c1;
        upk2(c0, c1, acc[j]);
        int h0 = hg*8 + 2*j, h1 = h0 + 1;
        ctx[((size_t)b*NH_ + h0)*H_ + d0 + dl] = c0;
        ctx[((size_t)b*NH_ + h1)*H_ + d0 + dl] = c1;
    }
}

// ---------------- LSTM elementwise ----------------
__device__ __forceinline__ float sigm(float x) { return 1.f / (1.f + __expf(-x)); }

__global__ void k_lstm(const float* __restrict__ gates,
                       const float* __restrict__ bih,
                       const float* __restrict__ bhh,
                       const float* __restrict__ c_in,
                       float* __restrict__ out)
{
    int idx = blockIdx.x * 256 + threadIdx.x;
    if (idx >= B_ * H_) return;
    int b = idx / H_, o = idx % H_;
    const float* g = gates + (size_t)b * 4 * H_;

    float ig = sigm (g[0*H_ + o] + bih[0*H_ + o] + bhh[0*H_ + o]);
    float fg = sigm (g[1*H_ + o] + bih[1*H_ + o] + bhh[1*H_ + o]);
    float gg = tanhf(g[2*H_ + o] + bih[2*H_ + o] + bhh[2*H_ + o]);
    float og = sigm (g[3*H_ + o] + bih[3*H_ + o] + bhh[3*H_ + o]);

    float c = fg * c_in[idx] + ig * gg;
    float h = og * tanhf(c);

    out[(size_t)B_ * V_ + idx] = h;
    out[(size_t)B_ * V_ + (size_t)B_ * H_ + idx] = c;
}

// ---------------- launcher ----------------
extern "C" void kernel_launch(void* const* d_in, const int* in_sizes, int n_in,
                              void* d_out, int out_size)
{
    const int*   tok   = (const int*)  d_in[0];
    const float* enc   = (const float*)d_in[1];
    const float* h_in  = (const float*)d_in[2];
    const float* c_in  = (const float*)d_in[3];
    const float* cache = (const float*)d_in[4];
    const int*   stepp = (const int*)  d_in[5];
    const float* table = (const float*)d_in[6];
    const float* saqw = (const float*)d_in[7];
    const float* saqb = (const float*)d_in[8];
    const float* sakw = (const float*)d_in[9];
    const float* sakb = (const float*)d_in[10];
    const float* savw = (const float*)d_in[11];
    const float* savb = (const float*)d_in[12];
    const float* caqw = (const float*)d_in[13];
    const float* caqb = (const float*)d_in[14];
    const float* cakw = (const float*)d_in[15];
    const float* cakb = (const float*)d_in[16];
    const float* cavw = (const float*)d_in[17];
    const float* cavb = (const float*)d_in[18];
    const float* wih  = (const float*)d_in[19];
    const float* bih  = (const float*)d_in[20];
    const float* whh  = (const float*)d_in[21];
    const float* bhh  = (const float*)d_in[22];
    const float* fcw  = (const float*)d_in[23];
    const float* fcb  = (const float*)d_in[24];
    float* out = (float*)d_out;

    float* sb = nullptr;
    cudaGetSymbolAddress((void**)&sb, g_scratch);

    float* p_emb  = sb + OF_EMB;
    float* p_Q    = sb + OF_Q;
    float* p_qt   = sb + OF_QT;
    float* p_qc   = sb + OF_QC;
    float* p_sc   = sb + OF_SC;
    float* p_ctx  = sb + OF_CTX;
    float* p_sao  = sb + OF_SAO;
    float* p_cao  = sb + OF_CAO;
    float* p_gate = sb + OF_GATE;
    float* p_hnew = out + (size_t)B_ * V_;

    k_gather<<<B_, 256>>>(tok, table, p_emb);

    // ---- self-attention ----
    k_zero<<<(B_*H_)/1024, 256>>>(p_Q, B_*H_);
    k_gemm2<<<dim3(H_/128, 1, 4), 256>>>(p_emb, H_, 0, saqw, H_, 0, saqb, 0,
                                         p_Q, H_, 0, H_, H_, 2);
    k_qt<<<dim3(H_/64, NH_), 256>>>(p_Q, sakw, sakb, p_qt, p_qc);
    k_scores<<<dim3(MAXLEN_/256, B_), 256>>>(p_qt, p_qc, cache,
                                             (long long)MAXLEN_ * H_,
                                             p_sc, MAXLEN_, stepp);
    k_softmax<<<B_ * NH_, 256>>>(p_sc, MAXLEN_, stepp);
    k_ctx<<<dim3(H_/128, B_), 256>>>(p_sc, cache, (long long)MAXLEN_ * H_,
                                     p_ctx, MAXLEN_, stepp);
    k_zero<<<(B_*H_)/1024, 256>>>(p_sao, B_*H_);
    k_gemm2<<<dim3(1, NH_, 4), 256>>>(p_ctx, NH_*H_, (long long)H_,
                                      savw, H_, (long long)HD_*H_,
                                      savb, HD_,
                                      p_sao, H_, (long long)HD_,
                                      HD_, H_, 2);

    // ---- cross-attention ----
    k_zero<<<(B_*H_)/1024, 256>>>(p_Q, B_*H_);
    k_gemm2<<<dim3(H_/128, 1, 4), 256>>>(p_sao, H_, 0, caqw, H_, 0, caqb, 0,
                                         p_Q, H_, 0, H_, H_, 2);
    k_qt<<<dim3(H_/64, NH_), 256>>>(p_Q, cakw, cakb, p_qt, p_qc);
    k_scores<<<dim3(S_/256, B_), 256>>>(p_qt, p_qc, enc,
                                        (long long)S_ * H_,
                                        p_sc, S_, nullptr);
    k_softmax<<<B_ * NH_, 256>>>(p_sc, S_, nullptr);
    k_ctx<<<dim3(H_/128, B_), 256>>>(p_sc, enc, (long long)S_ * H_,
                                     p_ctx, S_, nullptr);
    k_zero<<<(B_*H_)/1024, 256>>>(p_cao, B_*H_);
    k_gemm2<<<dim3(1, NH_, 4), 256>>>(p_ctx, NH_*H_, (long long)H_,
                                      cavw, H_, (long long)HD_*H_,
                                      cavb, HD_,
                                      p_cao, H_, (long long)HD_,
                                      HD_, H_, 2);

    // ---- LSTM gates (split-K atomic accumulate into zeroed buffer) ----
    k_zero<<<(B_*4*H_)/1024, 256>>>(p_gate, B_*4*H_);
    k_gemm2<<<dim3(4*H_/128, 1, 2), 256>>>(p_emb, H_, 0, wih,      2*H_, 0, nullptr, 0,
                                           p_gate, 4*H_, 0, 4*H_, H_, 2);
    k_gemm2<<<dim3(4*H_/128, 1, 2), 256>>>(p_cao, H_, 0, wih + H_, 2*H_, 0, nullptr, 0,
                                           p_gate, 4*H_, 0, 4*H_, H_, 2);
    k_gemm2<<<dim3(4*H_/128, 1, 2), 256>>>(h_in,  H_, 0, whh,      H_,   0, nullptr, 0,
                                           p_gate, 4*H_, 0, 4*H_, H_, 2);

    k_lstm<<<(B_*H_ + 255)/256, 256>>>(p_gate, bih, bhh, c_in, out);

    // ---- logits = h_new @ fc_w^T + fc_b ----
    k_gemm2<<<dim3((V_ + 127)/128, 1, 1), 256>>>(p_hnew, H_, 0, fcw, H_, 0, fcb, 0,
                                                 out, V_, 0, V_, H_, 0);
}

// round 6
// speedup vs baseline: 1.6287x; 1.2800x over previous
#include <cuda_runtime.h>
#include <math.h>

// Problem constants
#define B_    64
#define S_    2048
#define H_    1024
#define NH_   16
#define HD_   64
#define V_    50257
#define MAXLEN_ 1024
#define SLD_  2048
#define SCALE_ 0.125f

typedef unsigned long long u64;

__device__ __forceinline__ u64 pk2(float a, float b) {
    u64 r; asm("mov.b64 %0,{%1,%2};" : "=l"(r) : "f"(a), "f"(b)); return r;
}
__device__ __forceinline__ u64 dup2f(float a) { return pk2(a, a); }
__device__ __forceinline__ void fma2(u64& d, u64 a, u64 b) {
    asm("fma.rn.f32x2 %0,%1,%2,%0;" : "+l"(d) : "l"(a), "l"(b));
}
__device__ __forceinline__ void upk2(float& x, float& y, u64 v) {
    asm("mov.b64 {%0,%1},%2;" : "=f"(x), "=f"(y) : "l"(v));
}

// ---------------- scratch ----------
#define OF_EMB   ((size_t)0)
#define OF_Q     (OF_EMB  + (size_t)B_*H_)
#define OF_QT    (OF_Q    + (size_t)B_*H_)
#define OF_QC    (OF_QT   + (size_t)B_*NH_*H_)
#define OF_SC    (OF_QC   + (size_t)1024)
#define OF_CTX   (OF_SC   + (size_t)B_*NH_*SLD_)
#define OF_SAO   (OF_CTX  + (size_t)B_*NH_*H_)
#define OF_CAO   (OF_SAO  + (size_t)B_*H_)
#define OF_GATE  (OF_CAO  + (size_t)B_*H_)
#define SCRATCH_ (OF_GATE + (size_t)B_*4*H_)

__device__ float g_scratch[SCRATCH_];

// ---------------- zero ----------------
__global__ void k_zero(float* __restrict__ p, int n)
{
    int i = blockIdx.x * 1024 + threadIdx.x * 4;
    if (i < n) *(float4*)(p + i) = make_float4(0.f, 0.f, 0.f, 0.f);
}

// ---------------- embedding gather ----------------
__global__ void k_gather(const int* __restrict__ tok,
                         const float* __restrict__ table,
                         float* __restrict__ out)
{
    int b = blockIdx.x;
    int t = tok[b];
    const float4* src = (const float4*)(table + (size_t)t * H_);
    float4* dst = (float4*)(out + (size_t)b * H_);
    for (int i = threadIdx.x; i < H_/4; i += blockDim.x) dst[i] = src[i];
}

// ---------------- SGEMM: C[64 x N] = A[64 x K] @ B[N x K]^T (+bias) ---------
// 256 threads, block tile 64m x 128n, K-step 32, thread tile 4m x 8n, f32x2,
// register double-buffered loads.
// mode: 0 = write (+bias), 1 = serial accumulate, 2 = atomicAdd into
// pre-zeroed C (bias added only by z-slice 0).  grid.z = K split slices.
__global__ __launch_bounds__(256) void k_gemm2(
        const float* __restrict__ A, int lda, long long sA,
        const float* __restrict__ Bw, int ldb, long long sB,
        const float* __restrict__ bias, long long sBias,
        float* __restrict__ C, int ldc, long long sC,
        int N, int K, int mode)
{
    int bat = blockIdx.y;
    A  += (size_t)bat * sA;
    Bw += (size_t)bat * sB;
    C  += (size_t)bat * sC;
    if (bias) bias += (size_t)bat * sBias;

    int kper = K / gridDim.z;
    int kbeg = blockIdx.z * kper;
    int kend = kbeg + kper;
    bool addb = (bias != nullptr) && (blockIdx.z == 0);

    __shared__ float As[32 * 68];
    __shared__ float Bs[32 * 132];

    int t  = threadIdx.x;
    int n0 = blockIdx.x * 128;
    int tm = (t / 16) * 4;
    int tn = (t % 16) * 8;

    int lr = t / 8;
    int k4 = (t % 8) * 4;

    u64 acc2[4][4];
#pragma unroll
    for (int i = 0; i < 4; i++)
#pragma unroll
        for (int j = 0; j < 4; j++) acc2[i][j] = 0ULL;

    float4 pfa[2], pfb[4];
    // prefetch first slab
#pragma unroll
    for (int p = 0; p < 2; p++)
        pfa[p] = *(const float4*)&A[(size_t)(lr + p*32) * lda + kbeg + k4];
#pragma unroll
    for (int p = 0; p < 4; p++) {
        int gn = n0 + lr + p * 32;
        pfb[p] = (gn < N) ? *(const float4*)&Bw[(size_t)gn * ldb + kbeg + k4]
                          : make_float4(0.f, 0.f, 0.f, 0.f);
    }

    for (int k0 = kbeg; k0 < kend; k0 += 32) {
#pragma unroll
        for (int p = 0; p < 2; p++) {
            int m = lr + p * 32;
            As[(k4+0)*68 + m] = pfa[p].x;
            As[(k4+1)*68 + m] = pfa[p].y;
            As[(k4+2)*68 + m] = pfa[p].z;
            As[(k4+3)*68 + m] = pfa[p].w;
        }
#pragma unroll
        for (int p = 0; p < 4; p++) {
            int n = lr + p * 32;
            Bs[(k4+0)*132 + n] = pfb[p].x;
            Bs[(k4+1)*132 + n] = pfb[p].y;
            Bs[(k4+2)*132 + n] = pfb[p].z;
            Bs[(k4+3)*132 + n] = pfb[p].w;
        }
        __syncthreads();

        if (k0 + 32 < kend) {
#pragma unroll
            for (int p = 0; p < 2; p++)
                pfa[p] = *(const float4*)&A[(size_t)(lr + p*32) * lda + k0 + 32 + k4];
#pragma unroll
            for (int p = 0; p < 4; p++) {
                int gn = n0 + lr + p * 32;
                pfb[p] = (gn < N) ? *(const float4*)&Bw[(size_t)gn * ldb + k0 + 32 + k4]
                                  : make_float4(0.f, 0.f, 0.f, 0.f);
            }
        }

#pragma unroll 4
        for (int kk = 0; kk < 32; kk++) {
            float4 a = *(const float4*)&As[kk*68 + tm];
            ulonglong2 b01 = *(const ulonglong2*)&Bs[kk*132 + tn];
            ulonglong2 b23 = *(const ulonglong2*)&Bs[kk*132 + tn + 4];
            u64 ad0 = dup2f(a.x), ad1 = dup2f(a.y), ad2 = dup2f(a.z), ad3 = dup2f(a.w);
            fma2(acc2[0][0], ad0, b01.x); fma2(acc2[0][1], ad0, b01.y);
            fma2(acc2[0][2], ad0, b23.x); fma2(acc2[0][3], ad0, b23.y);
            fma2(acc2[1][0], ad1, b01.x); fma2(acc2[1][1], ad1, b01.y);
            fma2(acc2[1][2], ad1, b23.x); fma2(acc2[1][3], ad1, b23.y);
            fma2(acc2[2][0], ad2, b01.x); fma2(acc2[2][1], ad2, b01.y);
            fma2(acc2[2][2], ad2, b23.x); fma2(acc2[2][3], ad2, b23.y);
            fma2(acc2[3][0], ad3, b01.x); fma2(acc2[3][1], ad3, b01.y);
            fma2(acc2[3][2], ad3, b23.x); fma2(acc2[3][3], ad3, b23.y);
        }
        __syncthreads();
    }

#pragma unroll
    for (int mi = 0; mi < 4; mi++) {
#pragma unroll
        for (int np = 0; np < 4; np++) {
            float c0, c1;
            upk2(c0, c1, acc2[mi][np]);
            int n = n0 + tn + np * 2;
            size_t base = (size_t)(tm + mi) * ldc;
#pragma unroll
            for (int q = 0; q < 2; q++) {
                float v = (q == 0) ? c0 : c1;
                int nn = n + q;
                if (nn < N) {
                    if (mode == 2) {
                        if (addb) v += bias[nn];
                        atomicAdd(&C[base + nn], v);
                    } else {
                        if (bias) v += bias[nn];
                        if (mode == 1) C[base + nn] += v;
                        else           C[base + nn]  = v;
                    }
                }
            }
        }
    }
}

// ---------------- q-tilde fold v2, TRANSPOSED output: qtT[b][d][h] ----------
// grid (8 d-blocks of 128, NH heads).  thread: 4 d (float4 W) x 8 batches.
__global__ __launch_bounds__(256) void k_qt(
        const float* __restrict__ Q,
        const float* __restrict__ Wk,
        const float* __restrict__ bk,
        float* __restrict__ qtT,
        float* __restrict__ qc)
{
    int h  = blockIdx.y;
    int t  = threadIdx.x;
    int d  = blockIdx.x * 128 + (t & 31) * 4;
    int bg = t >> 5;                 // 0..7 -> batches bg*8..bg*8+7

    __shared__ float Qs[64 * 64];    // [b][j]
    for (int i = t; i < 1024; i += 256) {
        int b = i >> 4, jq = i & 15;
        ((float4*)Qs)[i] = *(const float4*)&Q[(size_t)b * H_ + h * 64 + jq * 4];
    }
    __syncthreads();

    u64 acc[8][2];
#pragma unroll
    for (int i = 0; i < 8; i++) { acc[i][0] = 0ULL; acc[i][1] = 0ULL; }

#pragma unroll 4
    for (int j = 0; j < 64; j++) {
        float4 w4 = *(const float4*)&Wk[(size_t)(h * 64 + j) * H_ + d];
        u64 w01 = pk2(w4.x, w4.y), w23 = pk2(w4.z, w4.w);
#pragma unroll
        for (int bb = 0; bb < 8; bb++) {
            u64 qd = dup2f(Qs[(bg * 8 + bb) * 64 + j]);
            fma2(acc[bb][0], qd, w01);
            fma2(acc[bb][1], qd, w23);
        }
    }

#pragma unroll
    for (int bb = 0; bb < 8; bb++) {
        int b = bg * 8 + bb;
        float v0, v1, v2, v3;
        upk2(v0, v1, acc[bb][0]);
        upk2(v2, v3, acc[bb][1]);
        size_t base = ((size_t)b * H_ + d) * NH_ + h;
        qtT[base          ] = v0;
        qtT[base +     NH_] = v1;
        qtT[base + 2 * NH_] = v2;
        qtT[base + 3 * NH_] = v3;
    }

    if (blockIdx.x == 0 && t < 64) {
        int b = t;
        float s = 0.f;
        for (int j = 0; j < 64; j++) s += Qs[b * 64 + j] * bk[h * 64 + j];
        qc[b * NH_ + h] = s;
    }
}

// ---------------- scores v4: register double-buffered ------------------------
// block = (key tile of 256, batch). 256 threads; thread owns 2 keys x 8 heads.
__global__ __launch_bounds__(256) void k_scores(
        const float* __restrict__ qtT,
        const float* __restrict__ qc,
        const float* __restrict__ keys, long long kbstride,
        float* __restrict__ scores,
        int Lmax, const int* __restrict__ Lptr)
{
    int b  = blockIdx.y;
    int L  = Lptr ? Lptr[0] : Lmax;
    int k0 = blockIdx.x * 256;
    if (k0 >= L) return;

    __shared__ float ks[256 * 33];
    __shared__ float qs[32 * 16];

    int t = threadIdx.x;
    const float* kb = keys + (size_t)b * kbstride;
    const float* qb = qtT + (size_t)b * H_ * NH_;

    u64 acc[2][4];
#pragma unroll
    for (int i = 0; i < 2; i++)
#pragma unroll
        for (int j = 0; j < 4; j++) acc[i][j] = 0ULL;

    int row = t >> 3;           // 0..31
    int d4  = (t & 7) * 4;      // 0..28
    int kl  = t & 127;          // key lane
    int hg  = t >> 7;           // head half

    float4 pf[8], qpf;
    // prefetch slab 0
#pragma unroll
    for (int p = 0; p < 8; p++)
        pf[p] = *(const float4*)&kb[(size_t)(k0 + row + p*32) * H_ + d4];
    if (t < 128) qpf = ((const float4*)qb)[t];

    for (int d0 = 0; d0 < H_; d0 += 32) {
#pragma unroll
        for (int p = 0; p < 8; p++) {
            int k = row + p * 32;
            ks[k*33 + d4 + 0] = pf[p].x;
            ks[k*33 + d4 + 1] = pf[p].y;
            ks[k*33 + d4 + 2] = pf[p].z;
            ks[k*33 + d4 + 3] = pf[p].w;
        }
        if (t < 128) ((float4*)qs)[t] = qpf;
        __syncthreads();

        if (d0 + 32 < H_) {
#pragma unroll
            for (int p = 0; p < 8; p++)
                pf[p] = *(const float4*)&kb[(size_t)(k0 + row + p*32) * H_ + d0 + 32 + d4];
            if (t < 128) qpf = ((const float4*)(qb + (size_t)(d0 + 32) * NH_))[t];
        }

#pragma unroll 4
        for (int dd = 0; dd < 32; dd++) {
            u64 kd0 = dup2f(ks[kl*33 + dd]);
            u64 kd1 = dup2f(ks[(kl + 128)*33 + dd]);
            const u64* qp = (const u64*)&qs[dd*16 + hg*8];
#pragma unroll
            for (int j = 0; j < 4; j++) {
                u64 q2 = qp[j];
                fma2(acc[0][j], q2, kd0);
                fma2(acc[1][j], q2, kd1);
            }
        }
        __syncthreads();
    }

    int kA = k0 + kl, kB = kA + 128;
#pragma unroll
    for (int j = 0; j < 4; j++) {
        int h0 = hg*8 + 2*j, h1 = h0 + 1;
        float c0 = qc[b*NH_ + h0], c1 = qc[b*NH_ + h1];
        float s0, s1, s2, s3;
        upk2(s0, s1, acc[0][j]);
        upk2(s2, s3, acc[1][j]);
        if (kA < L) {
            scores[((size_t)b*NH_ + h0)*SLD_ + kA] = (s0 + c0) * SCALE_;
            scores[((size_t)b*NH_ + h1)*SLD_ + kA] = (s1 + c1) * SCALE_;
        }
        if (kB < L) {
            scores[((size_t)b*NH_ + h0)*SLD_ + kB] = (s2 + c0) * SCALE_;
            scores[((size_t)b*NH_ + h1)*SLD_ + kB] = (s3 + c1) * SCALE_;
        }
    }
}

// ---------------- softmax ----------------
__global__ void k_softmax(float* __restrict__ scores,
                          int Lmax, const int* __restrict__ Lptr)
{
    int L = Lptr ? Lptr[0] : Lmax;
    float* s = scores + (size_t)blockIdx.x * SLD_;
    int tid = threadIdx.x;

    float v[8];
    float mx = -1e30f;
#pragma unroll
    for (int i = 0; i < 8; i++) {
        int k = tid + i * 256;
        v[i] = (k < L) ? s[k] : -1e30f;
        mx = fmaxf(mx, v[i]);
    }
    __shared__ float red[256];
    red[tid] = mx; __syncthreads();
    for (int off = 128; off; off >>= 1) {
        if (tid < off) red[tid] = fmaxf(red[tid], red[tid + off]);
        __syncthreads();
    }
    mx = red[0]; __syncthreads();

    float sum = 0.f;
#pragma unroll
    for (int i = 0; i < 8; i++) { v[i] = __expf(v[i] - mx); sum += v[i]; }
    red[tid] = sum; __syncthreads();
    for (int off = 128; off; off >>= 1) {
        if (tid < off) red[tid] += red[tid + off];
        __syncthreads();
    }
    float inv = 1.f / red[0];
#pragma unroll
    for (int i = 0; i < 8; i++) {
        int k = tid + i * 256;
        if (k < L) s[k] = v[i] * inv;
    }
}

// ---------------- ctx v4: register double-buffered ---------------------------
// block = (d-chunk 128, batch). 256 threads; thread owns d = d0 + (t&127),
// head-group hg = t>>7 (8 heads = 4 f32x2 accs).
__global__ __launch_bounds__(256) void k_ctx(
        const float* __restrict__ w,
        const float* __restrict__ keys, long long kbstride,
        float* __restrict__ ctx,
        int Lmax, const int* __restrict__ Lptr)
{
    int b  = blockIdx.y;
    int d0 = blockIdx.x * 128;
    int L  = Lptr ? Lptr[0] : Lmax;
    int t  = threadIdx.x;

    __shared__ float es[32 * 132];
    __shared__ float ws[32 * 18];

    const float* kb = keys + (size_t)b * kbstride + d0;

    u64 acc[4];
#pragma unroll
    for (int i = 0; i < 4; i++) acc[i] = 0ULL;

    int dl = t & 127;
    int hg = t >> 7;
    int er = t >> 5;            // 0..7
    int ec = (t & 31) * 4;      // 0..124

    float4 epf[4];
    float  wpf[2];
    // prefetch chunk 0
#pragma unroll
    for (int p = 0; p < 4; p++)
        epf[p] = *(const float4*)&kb[(size_t)(er + p*8) * H_ + ec];
#pragma unroll
    for (int p = 0; p < 2; p++) {
        int idx = t + p * 256;
        int h = idx >> 5, kk = idx & 31;
        wpf[p] = (kk < L) ? w[((size_t)b*NH_ + h)*SLD_ + kk] : 0.f;
    }

    for (int k0 = 0; k0 < L; k0 += 32) {
#pragma unroll
        for (int p = 0; p < 4; p++)
            *(float4*)&es[(er + p*8)*132 + ec] = epf[p];
#pragma unroll
        for (int p = 0; p < 2; p++) {
            int idx = t + p * 256;
            int h = idx >> 5, kk = idx & 31;
            ws[kk*18 + h] = wpf[p];
        }
        __syncthreads();

        if (k0 + 32 < L) {
#pragma unroll
            for (int p = 0; p < 4; p++)
                epf[p] = *(const float4*)&kb[(size_t)(k0 + 32 + er + p*8) * H_ + ec];
#pragma unroll
            for (int p = 0; p < 2; p++) {
                int idx = t + p * 256;
                int h = idx >> 5, kk = idx & 31;
                int k = k0 + 32 + kk;
                wpf[p] = (k < L) ? w[((size_t)b*NH_ + h)*SLD_ + k] : 0.f;
            }
        }

#pragma unroll 4
        for (int kk = 0; kk < 32; kk++) {
            u64 e = dup2f(es[kk*132 + dl]);
            const u64* wp = (const u64*)&ws[kk*18 + hg*8];
#pragma unroll
            for (int j = 0; j < 4; j++)
                fma2(acc[j], wp[j], e);
        }
        __syncthreads();
    }

#pragma unroll
    for (int j = 0; j < 4; j++) {
        float c0, c1;
        upk2(c0, c1, acc[j]);
        int h0 = hg*8 + 2*j, h1 = h0 + 1;
        ctx[((size_t)b*NH_ + h0)*H_ + d0 + dl] = c0;
        ctx[((size_t)b*NH_ + h1)*H_ + d0 + dl] = c1;
    }
}

// ---------------- LSTM elementwise ----------------
__device__ __forceinline__ float sigm(float x) { return 1.f / (1.f + __expf(-x)); }

__global__ void k_lstm(const float* __restrict__ gates,
                       const float* __restrict__ bih,
                       const float* __restrict__ bhh,
                       const float* __restrict__ c_in,
                       float* __restrict__ out)
{
    int idx = blockIdx.x * 256 + threadIdx.x;
    if (idx >= B_ * H_) return;
    int b = idx / H_, o = idx % H_;
    const float* g = gates + (size_t)b * 4 * H_;

    float ig = sigm (g[0*H_ + o] + bih[0*H_ + o] + bhh[0*H_ + o]);
    float fg = sigm (g[1*H_ + o] + bih[1*H_ + o] + bhh[1*H_ + o]);
    float gg = tanhf(g[2*H_ + o] + bih[2*H_ + o] + bhh[2*H_ + o]);
    float og = sigm (g[3*H_ + o] + bih[3*H_ + o] + bhh[3*H_ + o]);

    float c = fg * c_in[idx] + ig * gg;
    float h = og * tanhf(c);

    out[(size_t)B_ * V_ + idx] = h;
    out[(size_t)B_ * V_ + (size_t)B_ * H_ + idx] = c;
}

// ---------------- launcher ----------------
extern "C" void kernel_launch(void* const* d_in, const int* in_sizes, int n_in,
                              void* d_out, int out_size)
{
    const int*   tok   = (const int*)  d_in[0];
    const float* enc   = (const float*)d_in[1];
    const float* h_in  = (const float*)d_in[2];
    const float* c_in  = (const float*)d_in[3];
    const float* cache = (const float*)d_in[4];
    const int*   stepp = (const int*)  d_in[5];
    const float* table = (const float*)d_in[6];
    const float* saqw = (const float*)d_in[7];
    const float* saqb = (const float*)d_in[8];
    const float* sakw = (const float*)d_in[9];
    const float* sakb = (const float*)d_in[10];
    const float* savw = (const float*)d_in[11];
    const float* savb = (const float*)d_in[12];
    const float* caqw = (const float*)d_in[13];
    const float* caqb = (const float*)d_in[14];
    const float* cakw = (const float*)d_in[15];
    const float* cakb = (const float*)d_in[16];
    const float* cavw = (const float*)d_in[17];
    const float* cavb = (const float*)d_in[18];
    const float* wih  = (const float*)d_in[19];
    const float* bih  = (const float*)d_in[20];
    const float* whh  = (const float*)d_in[21];
    const float* bhh  = (const float*)d_in[22];
    const float* fcw  = (const float*)d_in[23];
    const float* fcb  = (const float*)d_in[24];
    float* out = (float*)d_out;

    float* sb = nullptr;
    cudaGetSymbolAddress((void**)&sb, g_scratch);

    float* p_emb  = sb + OF_EMB;
    float* p_Q    = sb + OF_Q;
    float* p_qt   = sb + OF_QT;
    float* p_qc   = sb + OF_QC;
    float* p_sc   = sb + OF_SC;
    float* p_ctx  = sb + OF_CTX;
    float* p_sao  = sb + OF_SAO;
    float* p_cao  = sb + OF_CAO;
    float* p_gate = sb + OF_GATE;
    float* p_hnew = out + (size_t)B_ * V_;

    k_gather<<<B_, 256>>>(tok, table, p_emb);

    // ---- self-attention ----
    k_zero<<<(B_*H_)/1024, 256>>>(p_Q, B_*H_);
    k_gemm2<<<dim3(H_/128, 1, 4), 256>>>(p_emb, H_, 0, saqw, H_, 0, saqb, 0,
                                         p_Q, H_, 0, H_, H_, 2);
    k_qt<<<dim3(8, NH_), 256>>>(p_Q, sakw, sakb, p_qt, p_qc);
    k_scores<<<dim3(MAXLEN_/256, B_), 256>>>(p_qt, p_qc, cache,
                                             (long long)MAXLEN_ * H_,
                                             p_sc, MAXLEN_, stepp);
    k_softmax<<<B_ * NH_, 256>>>(p_sc, MAXLEN_, stepp);
    k_ctx<<<dim3(H_/128, B_), 256>>>(p_sc, cache, (long long)MAXLEN_ * H_,
                                     p_ctx, MAXLEN_, stepp);
    k_zero<<<(B_*H_)/1024, 256>>>(p_sao, B_*H_);
    k_gemm2<<<dim3(1, NH_, 4), 256>>>(p_ctx, NH_*H_, (long long)H_,
                                      savw, H_, (long long)HD_*H_,
                                      savb, HD_,
                                      p_sao, H_, (long long)HD_,
                                      HD_, H_, 2);

    // ---- cross-attention ----
    k_zero<<<(B_*H_)/1024, 256>>>(p_Q, B_*H_);
    k_gemm2<<<dim3(H_/128, 1, 4), 256>>>(p_sao, H_, 0, caqw, H_, 0, caqb, 0,
                                         p_Q, H_, 0, H_, H_, 2);
    k_qt<<<dim3(8, NH_), 256>>>(p_Q, cakw, cakb, p_qt, p_qc);
    k_scores<<<dim3(S_/256, B_), 256>>>(p_qt, p_qc, enc,
                                        (long long)S_ * H_,
                                        p_sc, S_, nullptr);
    k_softmax<<<B_ * NH_, 256>>>(p_sc, S_, nullptr);
    k_ctx<<<dim3(H_/128, B_), 256>>>(p_sc, enc, (long long)S_ * H_,
                                     p_ctx, S_, nullptr);
    k_zero<<<(B_*H_)/1024, 256>>>(p_cao, B_*H_);
    k_gemm2<<<dim3(1, NH_, 4), 256>>>(p_ctx, NH_*H_, (long long)H_,
                                      cavw, H_, (long long)HD_*H_,
                                      cavb, HD_,
                                      p_cao, H_, (long long)HD_,
                                      HD_, H_, 2);

    // ---- LSTM gates (split-K atomic accumulate into zeroed buffer) ----
    k_zero<<<(B_*4*H_)/1024, 256>>>(p_gate, B_*4*H_);
    k_gemm2<<<dim3(4*H_/128, 1, 4), 256>>>(p_emb, H_, 0, wih,      2*H_, 0, nullptr, 0,
                                           p_gate, 4*H_, 0, 4*H_, H_, 2);
    k_gemm2<<<dim3(4*H_/128, 1, 4), 256>>>(p_cao, H_, 0, wih + H_, 2*H_, 0, nullptr, 0,
                                           p_gate, 4*H_, 0, 4*H_, H_, 2);
    k_gemm2<<<dim3(4*H_/128, 1, 4), 256>>>(h_in,  H_, 0, whh,      H_,   0, nullptr, 0,
                                           p_gate, 4*H_, 0, 4*H_, H_, 2);

    k_lstm<<<(B_*H_ + 255)/256, 256>>>(p_gate, bih, bhh, c_in, out);

    // ---- logits = h_new @ fc_w^T + fc_b ----
    k_gemm2<<<dim3((V_ + 127)/128, 1, 1), 256>>>(p_hnew, H_, 0, fcw, H_, 0, fcb, 0,
                                                 out, V_, 0, V_, H_, 0);
}